// round 3
// baseline (speedup 1.0000x reference)
#include <cuda_runtime.h>
#include <cuda_bf16.h>
#include <math.h>
#include <stdint.h>

// ---------------- problem constants ----------------
#define EDIM 4096
#define NH   32
#define HD   128
#define Lseq 8192          // 8*32*32
#define Bb   2
#define VD   1536
#define NQ   64
#define NROWS (Bb*Lseq)    // 16384

// ---------------- scratch (device globals; no allocations) ----------------
__device__ float g_kv[NROWS * EDIM];      // post-LN kv, (b*L+l, E)
__device__ float g_kvrot[NROWS * EDIM];
__device__ float g_kp[NROWS * EDIM];
__device__ float g_vp[NROWS * EDIM];
__device__ float g_scores[(size_t)Bb * NH * NQ * Lseq];  // ((b*32+h)*64+q, L)
__device__ float g_qn[NQ * EDIM];
__device__ float g_qp[NQ * EDIM];
__device__ float g_ctx[Bb * NQ * EDIM];   // row = b*64+q
__device__ float g_out1[Bb * NQ * EDIM];
__device__ float g_ln2[Bb * NQ * EDIM];

// ---------------- tf32 helpers ----------------
__device__ __forceinline__ uint32_t f2tf32(float x) {
    uint32_t r;
    asm("cvt.rna.tf32.f32 %0, %1;" : "=r"(r) : "f"(x));
    return r;
}

__device__ __forceinline__ void mma_tf32(float c[4],
                                         uint32_t a0, uint32_t a1, uint32_t a2, uint32_t a3,
                                         uint32_t b0, uint32_t b1) {
    asm("mma.sync.aligned.m16n8k8.row.col.f32.tf32.tf32.f32 "
        "{%0,%1,%2,%3}, {%4,%5,%6,%7}, {%8,%9}, {%0,%1,%2,%3};"
        : "+f"(c[0]), "+f"(c[1]), "+f"(c[2]), "+f"(c[3])
        : "r"(a0), "r"(a1), "r"(a2), "r"(a3), "r"(b0), "r"(b1));
}

// ---------------- tf32 GEMM: C = A . B^T + bias ----------------
// A: MxK row-major (lda), B: NxK row-major (ldb). Requires M%128==0, N%128==0, K%16==0.
#define TSTR 136  // smem row stride (floats): 136 % 32 == 8 -> conflict-free frag loads
__global__ __launch_bounds__(256)
void gemm_tn_tf32(const float* __restrict__ A, int lda,
                  const float* __restrict__ B, int ldb,
                  float* __restrict__ C, int ldc,
                  int M, int N, int K, const float* __restrict__ bias) {
    __shared__ uint32_t As[2][16 * TSTR];
    __shared__ uint32_t Bs[2][16 * TSTR];

    int tid = threadIdx.x;
    int lane = tid & 31;
    int wid = tid >> 5;
    int wm = (wid & 1) * 64;       // warp m offset within block
    int wn = (wid >> 1) * 32;      // warp n offset within block
    int m0 = blockIdx.y * 128, n0 = blockIdx.x * 128;

    int r    = tid >> 1;           // 0..127 (tile row)
    int koff = (tid & 1) * 8;      // 0 or 8

    const float* pA = A + (size_t)(m0 + r) * lda + koff;
    const float* pB = B + (size_t)(n0 + r) * ldb + koff;

    float acc[4][4][4];
#pragma unroll
    for (int i = 0; i < 4; i++)
#pragma unroll
        for (int j = 0; j < 4; j++)
#pragma unroll
            for (int t = 0; t < 4; t++) acc[i][j][t] = 0.f;

    // preload first tile
    {
        float4 a0 = *(const float4*)(pA);
        float4 a1 = *(const float4*)(pA + 4);
        float4 b0 = *(const float4*)(pB);
        float4 b1 = *(const float4*)(pB + 4);
        As[0][(koff + 0) * TSTR + r] = f2tf32(a0.x);
        As[0][(koff + 1) * TSTR + r] = f2tf32(a0.y);
        As[0][(koff + 2) * TSTR + r] = f2tf32(a0.z);
        As[0][(koff + 3) * TSTR + r] = f2tf32(a0.w);
        As[0][(koff + 4) * TSTR + r] = f2tf32(a1.x);
        As[0][(koff + 5) * TSTR + r] = f2tf32(a1.y);
        As[0][(koff + 6) * TSTR + r] = f2tf32(a1.z);
        As[0][(koff + 7) * TSTR + r] = f2tf32(a1.w);
        Bs[0][(koff + 0) * TSTR + r] = f2tf32(b0.x);
        Bs[0][(koff + 1) * TSTR + r] = f2tf32(b0.y);
        Bs[0][(koff + 2) * TSTR + r] = f2tf32(b0.z);
        Bs[0][(koff + 3) * TSTR + r] = f2tf32(b0.w);
        Bs[0][(koff + 4) * TSTR + r] = f2tf32(b1.x);
        Bs[0][(koff + 5) * TSTR + r] = f2tf32(b1.y);
        Bs[0][(koff + 6) * TSTR + r] = f2tf32(b1.z);
        Bs[0][(koff + 7) * TSTR + r] = f2tf32(b1.w);
    }
    __syncthreads();

    int buf = 0;
    for (int k0 = 0; k0 < K; k0 += 16) {
        bool last = (k0 + 16 >= K);
        float4 pa0, pa1, pb0, pb1;
        if (!last) {
            const float* qA = pA + k0 + 16;
            const float* qB = pB + k0 + 16;
            pa0 = *(const float4*)(qA);
            pa1 = *(const float4*)(qA + 4);
            pb0 = *(const float4*)(qB);
            pb1 = *(const float4*)(qB + 4);
        }

        const uint32_t* as = As[buf];
        const uint32_t* bs = Bs[buf];
#pragma unroll
        for (int kk = 0; kk < 16; kk += 8) {
            int kr = kk + (lane & 3);
            int mrow = wm + (lane >> 2);
            int ncol = wn + (lane >> 2);
            uint32_t af[4][4], bf[4][2];
#pragma unroll
            for (int i = 0; i < 4; i++) {
                af[i][0] = as[kr * TSTR + mrow + i * 16];
                af[i][1] = as[kr * TSTR + mrow + i * 16 + 8];
                af[i][2] = as[(kr + 4) * TSTR + mrow + i * 16];
                af[i][3] = as[(kr + 4) * TSTR + mrow + i * 16 + 8];
            }
#pragma unroll
            for (int j = 0; j < 4; j++) {
                bf[j][0] = bs[kr * TSTR + ncol + j * 8];
                bf[j][1] = bs[(kr + 4) * TSTR + ncol + j * 8];
            }
#pragma unroll
            for (int i = 0; i < 4; i++)
#pragma unroll
                for (int j = 0; j < 4; j++)
                    mma_tf32(acc[i][j], af[i][0], af[i][1], af[i][2], af[i][3],
                             bf[j][0], bf[j][1]);
        }

        if (!last) {
            int nb = buf ^ 1;
            As[nb][(koff + 0) * TSTR + r] = f2tf32(pa0.x);
            As[nb][(koff + 1) * TSTR + r] = f2tf32(pa0.y);
            As[nb][(koff + 2) * TSTR + r] = f2tf32(pa0.z);
            As[nb][(koff + 3) * TSTR + r] = f2tf32(pa0.w);
            As[nb][(koff + 4) * TSTR + r] = f2tf32(pa1.x);
            As[nb][(koff + 5) * TSTR + r] = f2tf32(pa1.y);
            As[nb][(koff + 6) * TSTR + r] = f2tf32(pa1.z);
            As[nb][(koff + 7) * TSTR + r] = f2tf32(pa1.w);
            Bs[nb][(koff + 0) * TSTR + r] = f2tf32(pb0.x);
            Bs[nb][(koff + 1) * TSTR + r] = f2tf32(pb0.y);
            Bs[nb][(koff + 2) * TSTR + r] = f2tf32(pb0.z);
            Bs[nb][(koff + 3) * TSTR + r] = f2tf32(pb0.w);
            Bs[nb][(koff + 4) * TSTR + r] = f2tf32(pb1.x);
            Bs[nb][(koff + 5) * TSTR + r] = f2tf32(pb1.y);
            Bs[nb][(koff + 6) * TSTR + r] = f2tf32(pb1.z);
            Bs[nb][(koff + 7) * TSTR + r] = f2tf32(pb1.w);
            __syncthreads();
            buf = nb;
        }
    }

    // epilogue
#pragma unroll
    for (int j = 0; j < 4; j++) {
        int col = n0 + wn + j * 8 + (lane & 3) * 2;
        float b0v = bias ? bias[col] : 0.f;
        float b1v = bias ? bias[col + 1] : 0.f;
#pragma unroll
        for (int i = 0; i < 4; i++) {
            int row = m0 + wm + i * 16 + (lane >> 2);
            float2 v0 = make_float2(acc[i][j][0] + b0v, acc[i][j][1] + b1v);
            float2 v1 = make_float2(acc[i][j][2] + b0v, acc[i][j][3] + b1v);
            *(float2*)&C[(size_t)row * ldc + col] = v0;
            *(float2*)&C[(size_t)(row + 8) * ldc + col] = v1;
        }
    }
}

// ---------------- fused LayerNorm + RoPE for kv (in-place LN + rotated copy) ----------------
__global__ void ln_rope_kernel(float* __restrict__ kv, float* __restrict__ kvrot,
                               const float* __restrict__ w, const float* __restrict__ b) {
    __shared__ __align__(16) float row[4096];
    __shared__ float red[256];
    int rix = blockIdx.x;            // b*L + l
    int l = rix & (Lseq - 1);
    size_t base = (size_t)rix * 4096;
    int tid = threadIdx.x;

    float s = 0.f;
    for (int i = tid; i < 4096; i += 256) { float v = kv[base + i]; row[i] = v; s += v; }
    red[tid] = s; __syncthreads();
    for (int off = 128; off > 0; off >>= 1) {
        if (tid < off) red[tid] += red[tid + off];
        __syncthreads();
    }
    float mean = red[0] * (1.f / 4096.f);
    __syncthreads();
    float vs = 0.f;
    for (int i = tid; i < 4096; i += 256) { float d = row[i] - mean; vs += d * d; }
    red[tid] = vs; __syncthreads();
    for (int off = 128; off > 0; off >>= 1) {
        if (tid < off) red[tid] += red[tid + off];
        __syncthreads();
    }
    float inv = rsqrtf(red[0] * (1.f / 4096.f) + 1e-6f);
    __syncthreads();

    // position values
    int t = l >> 10;
    int rem = l & 1023;
    float hh = (float)(rem >> 5);
    float ww = (float)(rem & 31);
    float pos = (float)t * (10.0f / 3.0f);
    float lo = floorf(pos); if (lo > 23.f) lo = 23.f;
    float hi = ceilf(pos);  if (hi > 23.f) hi = 23.f;
    float wgt = pos - lo;
    float pt = lo * (1.f - wgt) + hi * wgt;

    for (int i = tid; i < 2048; i += 256) {
        int j = 2 * i;
        float x1 = (row[j] - mean) * inv * w[j] + b[j];
        float x2 = (row[j + 1] - mean) * inv * w[j + 1] + b[j + 1];
        float theta;
        if (j < 1024) {
            int k = j & 511;
            theta = pt * powf(10000.f, -(float)(2 * k) / 1024.f);
        } else if (j < 2560) {
            int k = (j - 1024) % 768;
            theta = hh * powf(10000.f, -(float)(2 * k) / 1536.f);
        } else {
            int k = (j - 2560) % 768;
            theta = ww * powf(10000.f, -(float)(2 * k) / 1536.f);
        }
        float cc = cosf(theta), ss = sinf(theta);
        kv[base + j]     = x1;
        kv[base + j + 1] = x2;
        kvrot[base + j]     = x1 * cc - x2 * ss;
        kvrot[base + j + 1] = x1 * ss + x2 * cc;
    }
}

// ---------------- plain LayerNorm over 4096 cols (small row counts) ----------------
__global__ void ln_kernel(const float* __restrict__ in, float* __restrict__ out,
                          const float* __restrict__ w, const float* __restrict__ b) {
    __shared__ __align__(16) float row[4096];
    __shared__ float red[256];
    size_t base = (size_t)blockIdx.x * 4096;
    int tid = threadIdx.x;
    float s = 0.f;
    for (int i = tid; i < 4096; i += 256) { float v = in[base + i]; row[i] = v; s += v; }
    red[tid] = s; __syncthreads();
    for (int off = 128; off > 0; off >>= 1) {
        if (tid < off) red[tid] += red[tid + off];
        __syncthreads();
    }
    float mean = red[0] * (1.f / 4096.f);
    __syncthreads();
    float vs = 0.f;
    for (int i = tid; i < 4096; i += 256) { float d = row[i] - mean; vs += d * d; }
    red[tid] = vs; __syncthreads();
    for (int off = 128; off > 0; off >>= 1) {
        if (tid < off) red[tid] += red[tid + off];
        __syncthreads();
    }
    float inv = rsqrtf(red[0] * (1.f / 4096.f) + 1e-6f);
    for (int i = tid; i < 4096; i += 256)
        out[base + i] = (row[i] - mean) * inv * w[i] + b[i];
}

// ---------------- fp32 GEMM: C = A . B^T + bias (small M) ----------------
__global__ __launch_bounds__(256)
void gemm_tn(const float* __restrict__ A, int lda,
             const float* __restrict__ B, int ldb,
             float* __restrict__ C, int ldc,
             int M, int N, int K,
             const float* __restrict__ bias, float alpha) {
    __shared__ __align__(16) float As[8][128];
    __shared__ __align__(16) float Bs[8][128];
    int tid = threadIdx.x;
    int m0 = blockIdx.y * 128, n0 = blockIdx.x * 128;
    int arow = tid >> 1;
    int acol = (tid & 1) * 4;
    int ty = tid >> 4, tx = tid & 15;

    float acc[8][8];
#pragma unroll
    for (int i = 0; i < 8; i++)
#pragma unroll
        for (int j = 0; j < 8; j++) acc[i][j] = 0.f;

    for (int k0 = 0; k0 < K; k0 += 8) {
        float4 av = make_float4(0.f, 0.f, 0.f, 0.f);
        int gm = m0 + arow;
        if (gm < M) av = *(const float4*)&A[(size_t)gm * lda + k0 + acol];
        As[acol + 0][arow] = av.x; As[acol + 1][arow] = av.y;
        As[acol + 2][arow] = av.z; As[acol + 3][arow] = av.w;
        float4 bv = make_float4(0.f, 0.f, 0.f, 0.f);
        int gn = n0 + arow;
        if (gn < N) bv = *(const float4*)&B[(size_t)gn * ldb + k0 + acol];
        Bs[acol + 0][arow] = bv.x; Bs[acol + 1][arow] = bv.y;
        Bs[acol + 2][arow] = bv.z; Bs[acol + 3][arow] = bv.w;
        __syncthreads();
#pragma unroll
        for (int kk = 0; kk < 8; kk++) {
            float4 a0 = *(const float4*)&As[kk][ty * 8];
            float4 a1 = *(const float4*)&As[kk][ty * 8 + 4];
            float4 b0 = *(const float4*)&Bs[kk][tx * 8];
            float4 b1 = *(const float4*)&Bs[kk][tx * 8 + 4];
            float a[8] = {a0.x, a0.y, a0.z, a0.w, a1.x, a1.y, a1.z, a1.w};
            float bb[8] = {b0.x, b0.y, b0.z, b0.w, b1.x, b1.y, b1.z, b1.w};
#pragma unroll
            for (int i = 0; i < 8; i++)
#pragma unroll
                for (int j = 0; j < 8; j++)
                    acc[i][j] = fmaf(a[i], bb[j], acc[i][j]);
        }
        __syncthreads();
    }
#pragma unroll
    for (int i = 0; i < 8; i++) {
        int gm = m0 + ty * 8 + i;
        if (gm >= M) continue;
#pragma unroll
        for (int j = 0; j < 8; j++) {
            int gn = n0 + tx * 8 + j;
            if (gn >= N) continue;
            float v = acc[i][j] * alpha;
            if (bias) v += bias[gn];
            C[(size_t)gm * ldc + gn] = v;
        }
    }
}

// ---------------- fp32 GEMM: C = A . B (small M) ----------------
__global__ __launch_bounds__(256)
void gemm_nn(const float* __restrict__ A, int lda,
             const float* __restrict__ B, int ldb,
             float* __restrict__ C, int ldc,
             int M, int N, int K) {
    __shared__ __align__(16) float As[8][128];
    __shared__ __align__(16) float Bs[8][128];
    int tid = threadIdx.x;
    int m0 = blockIdx.y * 128, n0 = blockIdx.x * 128;
    int arow = tid >> 1;
    int acol = (tid & 1) * 4;
    int bkr = tid >> 5;
    int bnc = (tid & 31) * 4;
    int ty = tid >> 4, tx = tid & 15;

    float acc[8][8];
#pragma unroll
    for (int i = 0; i < 8; i++)
#pragma unroll
        for (int j = 0; j < 8; j++) acc[i][j] = 0.f;

    for (int k0 = 0; k0 < K; k0 += 8) {
        float4 av = make_float4(0.f, 0.f, 0.f, 0.f);
        int gm = m0 + arow;
        if (gm < M) av = *(const float4*)&A[(size_t)gm * lda + k0 + acol];
        As[acol + 0][arow] = av.x; As[acol + 1][arow] = av.y;
        As[acol + 2][arow] = av.z; As[acol + 3][arow] = av.w;
        float4 bv = make_float4(0.f, 0.f, 0.f, 0.f);
        int gn = n0 + bnc;
        if (gn < N) bv = *(const float4*)&B[(size_t)(k0 + bkr) * ldb + gn];
        *(float4*)&Bs[bkr][bnc] = bv;
        __syncthreads();
#pragma unroll
        for (int kk = 0; kk < 8; kk++) {
            float4 a0 = *(const float4*)&As[kk][ty * 8];
            float4 a1 = *(const float4*)&As[kk][ty * 8 + 4];
            float4 b0 = *(const float4*)&Bs[kk][tx * 8];
            float4 b1 = *(const float4*)&Bs[kk][tx * 8 + 4];
            float a[8] = {a0.x, a0.y, a0.z, a0.w, a1.x, a1.y, a1.z, a1.w};
            float bb[8] = {b0.x, b0.y, b0.z, b0.w, b1.x, b1.y, b1.z, b1.w};
#pragma unroll
            for (int i = 0; i < 8; i++)
#pragma unroll
                for (int j = 0; j < 8; j++)
                    acc[i][j] = fmaf(a[i], bb[j], acc[i][j]);
        }
        __syncthreads();
    }
#pragma unroll
    for (int i = 0; i < 8; i++) {
        int gm = m0 + ty * 8 + i;
        if (gm >= M) continue;
#pragma unroll
        for (int j = 0; j < 8; j++) {
            int gn = n0 + tx * 8 + j;
            if (gn >= N) continue;
            C[(size_t)gm * ldc + gn] = acc[i][j];
        }
    }
}

// ---------------- scores ----------------
__global__ __launch_bounds__(256)
void scores_kernel(const float* __restrict__ qp, const float* __restrict__ kp,
                   float* __restrict__ scores) {
    int kt = blockIdx.x;
    int h = blockIdx.y;
    int b = blockIdx.z;
    __shared__ __align__(16) float Qs[16][64];
    __shared__ __align__(16) float Ks[16][64];
    int tid = threadIdx.x;
    int ty = tid >> 4, tx = tid & 15;
    float acc[4][4];
#pragma unroll
    for (int i = 0; i < 4; i++)
#pragma unroll
        for (int j = 0; j < 4; j++) acc[i][j] = 0.f;

    const float* qbase = qp + h * HD;
    const float* kbase = kp + ((size_t)b * Lseq + kt * 64) * EDIM + h * HD;
    int r = tid >> 2;
    int c = (tid & 3) * 4;

    for (int d0 = 0; d0 < HD; d0 += 16) {
        float4 qv = *(const float4*)&qbase[(size_t)r * EDIM + d0 + c];
        Qs[c + 0][r] = qv.x; Qs[c + 1][r] = qv.y; Qs[c + 2][r] = qv.z; Qs[c + 3][r] = qv.w;
        float4 kv4 = *(const float4*)&kbase[(size_t)r * EDIM + d0 + c];
        Ks[c + 0][r] = kv4.x; Ks[c + 1][r] = kv4.y; Ks[c + 2][r] = kv4.z; Ks[c + 3][r] = kv4.w;
        __syncthreads();
#pragma unroll
        for (int dd = 0; dd < 16; dd++) {
            float4 a = *(const float4*)&Qs[dd][ty * 4];
            float4 bb = *(const float4*)&Ks[dd][tx * 4];
            float av[4] = {a.x, a.y, a.z, a.w};
            float bv[4] = {bb.x, bb.y, bb.z, bb.w};
#pragma unroll
            for (int i = 0; i < 4; i++)
#pragma unroll
                for (int j = 0; j < 4; j++)
                    acc[i][j] = fmaf(av[i], bv[j], acc[i][j]);
        }
        __syncthreads();
    }
    const float sc = 0.08838834764831845f;
    size_t base = ((size_t)(b * NH + h) * NQ) * Lseq;
#pragma unroll
    for (int i = 0; i < 4; i++)
#pragma unroll
        for (int j = 0; j < 4; j++)
            scores[base + (size_t)(ty * 4 + i) * Lseq + kt * 64 + tx * 4 + j] = acc[i][j] * sc;
}

// ---------------- softmax ----------------
__global__ void softmax_kernel(float* __restrict__ s) {
    float* p = s + (size_t)blockIdx.x * Lseq;
    int tid = threadIdx.x;
    __shared__ float red[256];
    float mx = -1e30f;
    for (int i = tid; i < Lseq; i += 256) mx = fmaxf(mx, p[i]);
    red[tid] = mx; __syncthreads();
    for (int off = 128; off > 0; off >>= 1) {
        if (tid < off) red[tid] = fmaxf(red[tid], red[tid + off]);
        __syncthreads();
    }
    mx = red[0];
    __syncthreads();
    float sum = 0.f;
    for (int i = tid; i < Lseq; i += 256) {
        float e = expf(p[i] - mx);
        p[i] = e;
        sum += e;
    }
    red[tid] = sum; __syncthreads();
    for (int off = 128; off > 0; off >>= 1) {
        if (tid < off) red[tid] += red[tid + off];
        __syncthreads();
    }
    float inv = 1.f / red[0];
    __syncthreads();
    for (int i = tid; i < Lseq; i += 256) p[i] *= inv;
}

// ---------------- ctx ----------------
__global__ __launch_bounds__(256)
void ctx_kernel(const float* __restrict__ attn, const float* __restrict__ vp,
                float* __restrict__ ctx) {
    int ks = blockIdx.x;
    int h = blockIdx.y;
    int b = blockIdx.z;
    __shared__ __align__(16) float As[16][64];
    __shared__ __align__(16) float Vs[16][128];
    int tid = threadIdx.x;
    int qy = tid >> 4, dx = tid & 15;
    float acc[4][8];
#pragma unroll
    for (int i = 0; i < 4; i++)
#pragma unroll
        for (int j = 0; j < 8; j++) acc[i][j] = 0.f;

    int r = tid >> 2;
    int c = (tid & 3) * 4;
    int vr = tid >> 5;
    int vc = (tid & 31) * 4;
    size_t arow = (size_t)(b * NH + h) * NQ;

    for (int kc = 0; kc < 1024; kc += 16) {
        int kglob = ks * 1024 + kc;
        float4 av = *(const float4*)&attn[(arow + r) * Lseq + kglob + c];
        As[c + 0][r] = av.x; As[c + 1][r] = av.y; As[c + 2][r] = av.z; As[c + 3][r] = av.w;
#pragma unroll
        for (int p = 0; p < 2; p++) {
            int row = p * 8 + vr;
            float4 vv = *(const float4*)&vp[((size_t)(b * Lseq + kglob + row)) * EDIM + h * HD + vc];
            *(float4*)&Vs[row][vc] = vv;
        }
        __syncthreads();
#pragma unroll
        for (int kk = 0; kk < 16; kk++) {
            float4 a = *(const float4*)&As[kk][qy * 4];
            float av4[4] = {a.x, a.y, a.z, a.w};
            float4 v0 = *(const float4*)&Vs[kk][dx * 8];
            float4 v1 = *(const float4*)&Vs[kk][dx * 8 + 4];
            float vv[8] = {v0.x, v0.y, v0.z, v0.w, v1.x, v1.y, v1.z, v1.w};
#pragma unroll
            for (int i = 0; i < 4; i++)
#pragma unroll
                for (int j = 0; j < 8; j++)
                    acc[i][j] = fmaf(av4[i], vv[j], acc[i][j]);
        }
        __syncthreads();
    }
#pragma unroll
    for (int i = 0; i < 4; i++) {
        int q = qy * 4 + i;
#pragma unroll
        for (int j = 0; j < 8; j++)
            atomicAdd(&ctx[((size_t)(b * NQ + q)) * EDIM + h * HD + dx * 8 + j], acc[i][j]);
    }
}

// ---------------- launch ----------------
extern "C" void kernel_launch(void* const* d_in, const int* in_sizes, int n_in,
                              void* d_out, int out_size) {
    const float* cube      = (const float*)d_in[0];
    const float* query     = (const float*)d_in[1];
    const float* kv_proj_w = (const float*)d_in[2];
    const float* ln_q_w    = (const float*)d_in[3];
    const float* ln_q_b    = (const float*)d_in[4];
    const float* ln_kv_w   = (const float*)d_in[5];
    const float* ln_kv_b   = (const float*)d_in[6];
    const float* ln_post_w = (const float*)d_in[7];
    const float* ln_post_b = (const float*)d_in[8];
    const float* in_proj_w = (const float*)d_in[9];
    const float* in_proj_b = (const float*)d_in[10];
    const float* out_proj_w= (const float*)d_in[11];
    const float* out_proj_b= (const float*)d_in[12];
    const float* proj      = (const float*)d_in[13];
    float* out = (float*)d_out;

    float *kv, *kvrot, *kp, *vp, *scores, *qn, *qp, *ctx, *out1, *ln2;
    cudaGetSymbolAddress((void**)&kv,    g_kv);
    cudaGetSymbolAddress((void**)&kvrot, g_kvrot);
    cudaGetSymbolAddress((void**)&kp,    g_kp);
    cudaGetSymbolAddress((void**)&vp,    g_vp);
    cudaGetSymbolAddress((void**)&scores,g_scores);
    cudaGetSymbolAddress((void**)&qn,    g_qn);
    cudaGetSymbolAddress((void**)&qp,    g_qp);
    cudaGetSymbolAddress((void**)&ctx,   g_ctx);
    cudaGetSymbolAddress((void**)&out1,  g_out1);
    cudaGetSymbolAddress((void**)&ln2,   g_ln2);

    const size_t EE = (size_t)EDIM * EDIM;

    // kv = cube @ kv_proj_w^T (tf32 MMA) ; fused LN + RoPE
    gemm_tn_tf32<<<dim3(EDIM / 128, NROWS / 128), 256>>>(cube, VD, kv_proj_w, VD,
                                                         kv, EDIM, NROWS, EDIM, VD, nullptr);
    ln_rope_kernel<<<NROWS, 256>>>(kv, kvrot, ln_kv_w, ln_kv_b);

    // kp = kv_rot @ Wk^T + bk ; vp = kv @ Wv^T + bv (tf32 MMA)
    gemm_tn_tf32<<<dim3(EDIM / 128, NROWS / 128), 256>>>(kvrot, EDIM, in_proj_w + EE, EDIM,
                                                         kp, EDIM, NROWS, EDIM, EDIM,
                                                         in_proj_b + EDIM);
    gemm_tn_tf32<<<dim3(EDIM / 128, NROWS / 128), 256>>>(kv, EDIM, in_proj_w + 2 * EE, EDIM,
                                                         vp, EDIM, NROWS, EDIM, EDIM,
                                                         in_proj_b + 2 * EDIM);

    // q path (small, fp32)
    ln_kernel<<<NQ, 256>>>(query, qn, ln_q_w, ln_q_b);
    gemm_tn<<<dim3(EDIM / 128, 1), 256>>>(qn, EDIM, in_proj_w, EDIM,
                                          qp, EDIM, NQ, EDIM, EDIM, in_proj_b, 1.f);

    // attention
    scores_kernel<<<dim3(Lseq / 64, NH, Bb), 256>>>(qp, kp, scores);
    softmax_kernel<<<Bb * NH * NQ, 256>>>(scores);
    cudaMemsetAsync(ctx, 0, (size_t)Bb * NQ * EDIM * sizeof(float), 0);
    ctx_kernel<<<dim3(8, NH, Bb), 256>>>(scores, vp, ctx);

    // out proj + post LN + final proj (small, fp32)
    gemm_tn<<<dim3(EDIM / 128, 1), 256>>>(ctx, EDIM, out_proj_w, EDIM,
                                          out1, EDIM, Bb * NQ, EDIM, EDIM, out_proj_b, 1.f);
    ln_kernel<<<Bb * NQ, 256>>>(out1, ln2, ln_post_w, ln_post_b);
    gemm_nn<<<dim3(EDIM / 128, 1), 256>>>(ln2, EDIM, proj, EDIM,
                                          out, EDIM, Bb * NQ, EDIM, EDIM);
}

// round 4
// speedup vs baseline: 1.1969x; 1.1969x over previous
#include <cuda_runtime.h>
#include <math.h>
#include <stdint.h>

#define EDIM 4096
#define NH   32
#define HD   128
#define Lseq 8192
#define Bb   2
#define VD   1536
#define NQ   64
#define NROWS (Bb*Lseq)

// ---------------- scratch ----------------
__device__ float g_kv[NROWS * EDIM];
__device__ float g_kvrot[NROWS * EDIM];
__device__ float g_kvT[(size_t)Bb * EDIM * Lseq];
__device__ float g_scores[(size_t)Bb * NH * NQ * Lseq];
__device__ float g_qk[NH * NQ * EDIM];
__device__ float g_U[(size_t)Bb * NH * NQ * EDIM];
__device__ float g_qn[NQ * EDIM];
__device__ float g_qp[NQ * EDIM];
__device__ float g_ctx[Bb * NQ * EDIM];
__device__ float g_out1[Bb * NQ * EDIM];
__device__ float g_ln2[Bb * NQ * EDIM];

__device__ __forceinline__ uint32_t f2tf32(float x) {
    uint32_t r;
    asm("cvt.rna.tf32.f32 %0, %1;" : "=r"(r) : "f"(x));
    return r;
}
__device__ __forceinline__ void mma_tf32(float c[4],
                                         uint32_t a0, uint32_t a1, uint32_t a2, uint32_t a3,
                                         uint32_t b0, uint32_t b1) {
    asm("mma.sync.aligned.m16n8k8.row.col.f32.tf32.tf32.f32 "
        "{%0,%1,%2,%3}, {%4,%5,%6,%7}, {%8,%9}, {%0,%1,%2,%3};"
        : "+f"(c[0]), "+f"(c[1]), "+f"(c[2]), "+f"(c[3])
        : "r"(a0), "r"(a1), "r"(a2), "r"(a3), "r"(b0), "r"(b1));
}

// ---------------- tf32 GEMM v2: C = alpha * A . B^T ----------------
// A: M x K row-major, B: N x K row-major, both contraction-fastest.
// M%256==0, N%128==0, K%8==0. Batched over blockIdx.z with element strides.
#define SA 12
__global__ __launch_bounds__(256, 1)
void gemm_tf32_v2(const float* __restrict__ A, int lda, size_t sAz,
                  const float* __restrict__ B, int ldb, size_t sBz,
                  float* __restrict__ C, int ldc, size_t sCz,
                  int K, float alpha) {
    __shared__ uint32_t sAm[2][256 * SA];
    __shared__ uint32_t sBm[2][128 * SA];
    int t = threadIdx.x, lane = t & 31, wid = t >> 5;
    A += (size_t)blockIdx.z * sAz;
    B += (size_t)blockIdx.z * sBz;
    C += (size_t)blockIdx.z * sCz;
    int m0 = blockIdx.y * 256, n0 = blockIdx.x * 128;
    const float* pA = A + (size_t)(m0 + t) * lda;
    const float* pB = B + (size_t)(n0 + (t & 127)) * ldb;
    int wm = (wid & 3) * 64, wn = (wid >> 2) * 64;
    int lr = lane >> 2, lk = lane & 3;

    float acc[4][8][4];
#pragma unroll
    for (int i = 0; i < 4; i++)
#pragma unroll
        for (int j = 0; j < 8; j++)
#pragma unroll
            for (int v = 0; v < 4; v++) acc[i][j][v] = 0.f;

    // prologue: stage 0
    {
        float4 v0 = *(const float4*)(pA);
        float4 v1 = *(const float4*)(pA + 4);
        uint4 u0, u1;
        u0.x = f2tf32(v0.x); u0.y = f2tf32(v0.y); u0.z = f2tf32(v0.z); u0.w = f2tf32(v0.w);
        u1.x = f2tf32(v1.x); u1.y = f2tf32(v1.y); u1.z = f2tf32(v1.z); u1.w = f2tf32(v1.w);
        *(uint4*)&sAm[0][t * SA]     = u0;
        *(uint4*)&sAm[0][t * SA + 4] = u1;
        if (t < 128) {
            float4 w0 = *(const float4*)(pB);
            float4 w1 = *(const float4*)(pB + 4);
            uint4 x0, x1;
            x0.x = f2tf32(w0.x); x0.y = f2tf32(w0.y); x0.z = f2tf32(w0.z); x0.w = f2tf32(w0.w);
            x1.x = f2tf32(w1.x); x1.y = f2tf32(w1.y); x1.z = f2tf32(w1.z); x1.w = f2tf32(w1.w);
            *(uint4*)&sBm[0][t * SA]     = x0;
            *(uint4*)&sBm[0][t * SA + 4] = x1;
        }
    }
    __syncthreads();

    int st = 0;
    for (int k0 = 0; k0 < K; k0 += 8) {
        bool more = (k0 + 8) < K;
        float4 v0, v1, w0, w1;
        if (more) {
            v0 = *(const float4*)(pA + k0 + 8);
            v1 = *(const float4*)(pA + k0 + 12);
            if (t < 128) {
                w0 = *(const float4*)(pB + k0 + 8);
                w1 = *(const float4*)(pB + k0 + 12);
            }
        }
        const uint32_t* as = sAm[st];
        const uint32_t* bs = sBm[st];
        uint32_t bf[8][2];
#pragma unroll
        for (int j = 0; j < 8; j++) {
            int n = (wn + j * 8 + lr) * SA + lk;
            bf[j][0] = bs[n];
            bf[j][1] = bs[n + 4];
        }
#pragma unroll
        for (int i = 0; i < 4; i++) {
            int m = (wm + i * 16 + lr) * SA + lk;
            uint32_t a0 = as[m], a1 = as[m + 8 * SA];
            uint32_t a2 = as[m + 4], a3 = as[m + 8 * SA + 4];
#pragma unroll
            for (int j = 0; j < 8; j++)
                mma_tf32(acc[i][j], a0, a1, a2, a3, bf[j][0], bf[j][1]);
        }
        if (more) {
            int ns = st ^ 1;
            uint4 u0, u1;
            u0.x = f2tf32(v0.x); u0.y = f2tf32(v0.y); u0.z = f2tf32(v0.z); u0.w = f2tf32(v0.w);
            u1.x = f2tf32(v1.x); u1.y = f2tf32(v1.y); u1.z = f2tf32(v1.z); u1.w = f2tf32(v1.w);
            *(uint4*)&sAm[ns][t * SA]     = u0;
            *(uint4*)&sAm[ns][t * SA + 4] = u1;
            if (t < 128) {
                uint4 x0, x1;
                x0.x = f2tf32(w0.x); x0.y = f2tf32(w0.y); x0.z = f2tf32(w0.z); x0.w = f2tf32(w0.w);
                x1.x = f2tf32(w1.x); x1.y = f2tf32(w1.y); x1.z = f2tf32(w1.z); x1.w = f2tf32(w1.w);
                *(uint4*)&sBm[ns][t * SA]     = x0;
                *(uint4*)&sBm[ns][t * SA + 4] = x1;
            }
            __syncthreads();
            st = ns;
        }
    }
#pragma unroll
    for (int i = 0; i < 4; i++) {
        int row = m0 + wm + i * 16 + lr;
#pragma unroll
        for (int j = 0; j < 8; j++) {
            int col = n0 + wn + j * 8 + lk * 2;
            float2 p0 = make_float2(acc[i][j][0] * alpha, acc[i][j][1] * alpha);
            float2 p1 = make_float2(acc[i][j][2] * alpha, acc[i][j][3] * alpha);
            *(float2*)&C[(size_t)row * ldc + col] = p0;
            *(float2*)&C[(size_t)(row + 8) * ldc + col] = p1;
        }
    }
}

// ---------------- fused LayerNorm + RoPE ----------------
__global__ void ln_rope_kernel(float* __restrict__ kv, float* __restrict__ kvrot,
                               const float* __restrict__ w, const float* __restrict__ b) {
    __shared__ __align__(16) float row[4096];
    __shared__ float red[256];
    int rix = blockIdx.x;
    int l = rix & (Lseq - 1);
    size_t base = (size_t)rix * 4096;
    int tid = threadIdx.x;

    float s = 0.f;
    for (int i = tid; i < 4096; i += 256) { float v = kv[base + i]; row[i] = v; s += v; }
    red[tid] = s; __syncthreads();
    for (int off = 128; off > 0; off >>= 1) {
        if (tid < off) red[tid] += red[tid + off];
        __syncthreads();
    }
    float mean = red[0] * (1.f / 4096.f);
    __syncthreads();
    float vs = 0.f;
    for (int i = tid; i < 4096; i += 256) { float d = row[i] - mean; vs += d * d; }
    red[tid] = vs; __syncthreads();
    for (int off = 128; off > 0; off >>= 1) {
        if (tid < off) red[tid] += red[tid + off];
        __syncthreads();
    }
    float inv = rsqrtf(red[0] * (1.f / 4096.f) + 1e-6f);
    __syncthreads();

    int tt = l >> 10;
    int rem = l & 1023;
    float hh = (float)(rem >> 5);
    float ww = (float)(rem & 31);
    float pos = (float)tt * (10.0f / 3.0f);
    float lo = floorf(pos); if (lo > 23.f) lo = 23.f;
    float hi = ceilf(pos);  if (hi > 23.f) hi = 23.f;
    float wgt = pos - lo;
    float pt = lo * (1.f - wgt) + hi * wgt;

    for (int i = tid; i < 2048; i += 256) {
        int j = 2 * i;
        float x1 = (row[j] - mean) * inv * w[j] + b[j];
        float x2 = (row[j + 1] - mean) * inv * w[j + 1] + b[j + 1];
        float theta;
        if (j < 1024) {
            int k = j & 511;
            theta = pt * powf(10000.f, -(float)(2 * k) / 1024.f);
        } else if (j < 2560) {
            int k = (j - 1024) % 768;
            theta = hh * powf(10000.f, -(float)(2 * k) / 1536.f);
        } else {
            int k = (j - 2560) % 768;
            theta = ww * powf(10000.f, -(float)(2 * k) / 1536.f);
        }
        float cc = cosf(theta), ss = sinf(theta);
        kv[base + j]        = x1;
        kv[base + j + 1]    = x2;
        kvrot[base + j]     = x1 * cc - x2 * ss;
        kvrot[base + j + 1] = x1 * ss + x2 * cc;
    }
}

// ---------------- plain LayerNorm ----------------
__global__ void ln_kernel(const float* __restrict__ in, float* __restrict__ out,
                          const float* __restrict__ w, const float* __restrict__ b) {
    __shared__ __align__(16) float row[4096];
    __shared__ float red[256];
    size_t base = (size_t)blockIdx.x * 4096;
    int tid = threadIdx.x;
    float s = 0.f;
    for (int i = tid; i < 4096; i += 256) { float v = in[base + i]; row[i] = v; s += v; }
    red[tid] = s; __syncthreads();
    for (int off = 128; off > 0; off >>= 1) {
        if (tid < off) red[tid] += red[tid + off];
        __syncthreads();
    }
    float mean = red[0] * (1.f / 4096.f);
    __syncthreads();
    float vs = 0.f;
    for (int i = tid; i < 4096; i += 256) { float d = row[i] - mean; vs += d * d; }
    red[tid] = vs; __syncthreads();
    for (int off = 128; off > 0; off >>= 1) {
        if (tid < off) red[tid] += red[tid + off];
        __syncthreads();
    }
    float inv = rsqrtf(red[0] * (1.f / 4096.f) + 1e-6f);
    for (int i = tid; i < 4096; i += 256)
        out[base + i] = (row[i] - mean) * inv * w[i] + b[i];
}

// ---------------- transpose: kvT[b][e][k] = kv[b*L+k][e] ----------------
__global__ void transpose_kernel(const float* __restrict__ in, float* __restrict__ out) {
    __shared__ float tile[32][33];
    int b = blockIdx.z;
    int k0 = blockIdx.x * 32, e0 = blockIdx.y * 32;
    const float* src = in + (size_t)b * Lseq * EDIM;
    float* dst = out + (size_t)b * EDIM * Lseq;
    int x = threadIdx.x, y = threadIdx.y;
    for (int i = y; i < 32; i += 8)
        tile[i][x] = src[(size_t)(k0 + i) * EDIM + e0 + x];
    __syncthreads();
    for (int i = y; i < 32; i += 8)
        dst[(size_t)(e0 + i) * Lseq + k0 + x] = tile[x][i];
}

// ---------------- softmax over L=8192 ----------------
__global__ void softmax_kernel(float* __restrict__ s) {
    float* p = s + (size_t)blockIdx.x * Lseq;
    int tid = threadIdx.x;
    __shared__ float red[256];
    float mx = -1e30f;
    for (int i = tid; i < Lseq; i += 256) mx = fmaxf(mx, p[i]);
    red[tid] = mx; __syncthreads();
    for (int off = 128; off > 0; off >>= 1) {
        if (tid < off) red[tid] = fmaxf(red[tid], red[tid + off]);
        __syncthreads();
    }
    mx = red[0];
    __syncthreads();
    float sum = 0.f;
    for (int i = tid; i < Lseq; i += 256) {
        float e = expf(p[i] - mx);
        p[i] = e;
        sum += e;
    }
    red[tid] = sum; __syncthreads();
    for (int off = 128; off > 0; off >>= 1) {
        if (tid < off) red[tid] += red[tid + off];
        __syncthreads();
    }
    float inv = 1.f / red[0];
    __syncthreads();
    for (int i = tid; i < Lseq; i += 256) p[i] *= inv;
}

// ---------------- fp32 TN GEMM body (small M), 128x128 tile ----------------
__device__ __forceinline__
void gemm_tn_body(const float* __restrict__ A, int lda,
                  const float* __restrict__ B, int ldb,
                  float* __restrict__ C, int ldc,
                  int M, int N, int K,
                  const float* __restrict__ bias,
                  int m0, int n0) {
    __shared__ __align__(16) float As[8][128];
    __shared__ __align__(16) float Bs[8][128];
    int tid = threadIdx.x;
    int arow = tid >> 1;
    int acol = (tid & 1) * 4;
    int ty = tid >> 4, tx = tid & 15;

    float acc[8][8];
#pragma unroll
    for (int i = 0; i < 8; i++)
#pragma unroll
        for (int j = 0; j < 8; j++) acc[i][j] = 0.f;

    for (int k0 = 0; k0 < K; k0 += 8) {
        float4 av = make_float4(0.f, 0.f, 0.f, 0.f);
        int gm = m0 + arow;
        if (gm < M) av = *(const float4*)&A[(size_t)gm * lda + k0 + acol];
        As[acol + 0][arow] = av.x; As[acol + 1][arow] = av.y;
        As[acol + 2][arow] = av.z; As[acol + 3][arow] = av.w;
        float4 bv = make_float4(0.f, 0.f, 0.f, 0.f);
        int gn = n0 + arow;
        if (gn < N) bv = *(const float4*)&B[(size_t)gn * ldb + k0 + acol];
        Bs[acol + 0][arow] = bv.x; Bs[acol + 1][arow] = bv.y;
        Bs[acol + 2][arow] = bv.z; Bs[acol + 3][arow] = bv.w;
        __syncthreads();
#pragma unroll
        for (int kk = 0; kk < 8; kk++) {
            float4 a0 = *(const float4*)&As[kk][ty * 8];
            float4 a1 = *(const float4*)&As[kk][ty * 8 + 4];
            float4 b0 = *(const float4*)&Bs[kk][tx * 8];
            float4 b1 = *(const float4*)&Bs[kk][tx * 8 + 4];
            float a[8] = {a0.x, a0.y, a0.z, a0.w, a1.x, a1.y, a1.z, a1.w};
            float bb[8] = {b0.x, b0.y, b0.z, b0.w, b1.x, b1.y, b1.z, b1.w};
#pragma unroll
            for (int i = 0; i < 8; i++)
#pragma unroll
                for (int j = 0; j < 8; j++)
                    acc[i][j] = fmaf(a[i], bb[j], acc[i][j]);
        }
        __syncthreads();
    }
#pragma unroll
    for (int i = 0; i < 8; i++) {
        int gm = m0 + ty * 8 + i;
        if (gm >= M) continue;
#pragma unroll
        for (int j = 0; j < 8; j++) {
            int gn = n0 + tx * 8 + j;
            if (gn >= N) continue;
            float v = acc[i][j];
            if (bias) v += bias[gn];
            C[(size_t)gm * ldc + gn] = v;
        }
    }
}

__global__ __launch_bounds__(256)
void gemm_tn_g(const float* A, int lda, const float* B, int ldb,
               float* C, int ldc, int M, int N, int K, const float* bias) {
    gemm_tn_body(A, lda, B, ldb, C, ldc, M, N, K, bias,
                 blockIdx.y * 128, blockIdx.x * 128);
}

// vproj: per (b,h): ctx[b*64+q][h*128+d] = U[(b*32+h)*64+q][:] . Wv_h[d][:] + bv_h[d]
__global__ __launch_bounds__(256)
void vproj_g(const float* U, const float* Wv, const float* bv, float* ctx) {
    int z = blockIdx.z;
    int b = z >> 5, h = z & 31;
    gemm_tn_body(U + (size_t)z * 64 * EDIM, EDIM,
                 Wv + (size_t)h * 128 * EDIM, EDIM,
                 ctx + (size_t)b * 64 * EDIM + h * 128, EDIM,
                 64, 128, EDIM, bv + h * 128, 0, 0);
}

// ---------------- fp32 NN GEMM (small M), batched ----------------
__global__ __launch_bounds__(256)
void gemm_nn_b(const float* __restrict__ A, int lda, size_t sAz,
               const float* __restrict__ B, int ldb, size_t sBz,
               float* __restrict__ C, int ldc, size_t sCz,
               int M, int N, int K) {
    __shared__ __align__(16) float As[8][128];
    __shared__ __align__(16) float Bs[8][128];
    A += (size_t)blockIdx.z * sAz;
    B += (size_t)blockIdx.z * sBz;
    C += (size_t)blockIdx.z * sCz;
    int tid = threadIdx.x;
    int m0 = blockIdx.y * 128, n0 = blockIdx.x * 128;
    int arow = tid >> 1;
    int acol = (tid & 1) * 4;
    int bkr = tid >> 5;
    int bnc = (tid & 31) * 4;
    int ty = tid >> 4, tx = tid & 15;

    float acc[8][8];
#pragma unroll
    for (int i = 0; i < 8; i++)
#pragma unroll
        for (int j = 0; j < 8; j++) acc[i][j] = 0.f;

    for (int k0 = 0; k0 < K; k0 += 8) {
        float4 av = make_float4(0.f, 0.f, 0.f, 0.f);
        int gm = m0 + arow;
        if (gm < M) av = *(const float4*)&A[(size_t)gm * lda + k0 + acol];
        As[acol + 0][arow] = av.x; As[acol + 1][arow] = av.y;
        As[acol + 2][arow] = av.z; As[acol + 3][arow] = av.w;
        float4 bv = make_float4(0.f, 0.f, 0.f, 0.f);
        int gn = n0 + bnc;
        if (gn < N) bv = *(const float4*)&B[(size_t)(k0 + bkr) * ldb + gn];
        *(float4*)&Bs[bkr][bnc] = bv;
        __syncthreads();
#pragma unroll
        for (int kk = 0; kk < 8; kk++) {
            float4 a0 = *(const float4*)&As[kk][ty * 8];
            float4 a1 = *(const float4*)&As[kk][ty * 8 + 4];
            float4 b0 = *(const float4*)&Bs[kk][tx * 8];
            float4 b1 = *(const float4*)&Bs[kk][tx * 8 + 4];
            float a[8] = {a0.x, a0.y, a0.z, a0.w, a1.x, a1.y, a1.z, a1.w};
            float bb[8] = {b0.x, b0.y, b0.z, b0.w, b1.x, b1.y, b1.z, b1.w};
#pragma unroll
            for (int i = 0; i < 8; i++)
#pragma unroll
                for (int j = 0; j < 8; j++)
                    acc[i][j] = fmaf(a[i], bb[j], acc[i][j]);
        }
        __syncthreads();
    }
#pragma unroll
    for (int i = 0; i < 8; i++) {
        int gm = m0 + ty * 8 + i;
        if (gm >= M) continue;
#pragma unroll
        for (int j = 0; j < 8; j++) {
            int gn = n0 + tx * 8 + j;
            if (gn >= N) continue;
            C[(size_t)gm * ldc + gn] = acc[i][j];
        }
    }
}

// ---------------- launch ----------------
extern "C" void kernel_launch(void* const* d_in, const int* in_sizes, int n_in,
                              void* d_out, int out_size) {
    const float* cube      = (const float*)d_in[0];
    const float* query     = (const float*)d_in[1];
    const float* kv_proj_w = (const float*)d_in[2];
    const float* ln_q_w    = (const float*)d_in[3];
    const float* ln_q_b    = (const float*)d_in[4];
    const float* ln_kv_w   = (const float*)d_in[5];
    const float* ln_kv_b   = (const float*)d_in[6];
    const float* ln_post_w = (const float*)d_in[7];
    const float* ln_post_b = (const float*)d_in[8];
    const float* in_proj_w = (const float*)d_in[9];
    const float* in_proj_b = (const float*)d_in[10];
    const float* out_proj_w= (const float*)d_in[11];
    const float* out_proj_b= (const float*)d_in[12];
    const float* proj      = (const float*)d_in[13];
    float* out = (float*)d_out;

    float *kv, *kvrot, *kvT, *scores, *qk, *U, *qn, *qp, *ctx, *out1, *ln2;
    cudaGetSymbolAddress((void**)&kv,    g_kv);
    cudaGetSymbolAddress((void**)&kvrot, g_kvrot);
    cudaGetSymbolAddress((void**)&kvT,   g_kvT);
    cudaGetSymbolAddress((void**)&scores,g_scores);
    cudaGetSymbolAddress((void**)&qk,    g_qk);
    cudaGetSymbolAddress((void**)&U,     g_U);
    cudaGetSymbolAddress((void**)&qn,    g_qn);
    cudaGetSymbolAddress((void**)&qp,    g_qp);
    cudaGetSymbolAddress((void**)&ctx,   g_ctx);
    cudaGetSymbolAddress((void**)&out1,  g_out1);
    cudaGetSymbolAddress((void**)&ln2,   g_ln2);

    const size_t EE = (size_t)EDIM * EDIM;
    const float isq = 0.08838834764831845f;  // 1/sqrt(128)

    // 1) kv = cube @ kv_proj_w^T (tf32)
    gemm_tf32_v2<<<dim3(EDIM / 128, NROWS / 256, 1), 256>>>(
        cube, VD, 0, kv_proj_w, VD, 0, kv, EDIM, 0, VD, 1.f);
    // 2) LN + RoPE
    ln_rope_kernel<<<NROWS, 256>>>(kv, kvrot, ln_kv_w, ln_kv_b);
    // 3) kvT = transpose(kv) per batch
    transpose_kernel<<<dim3(Lseq / 32, EDIM / 32, Bb), dim3(32, 8)>>>(kv, kvT);

    // 4) q path: LN -> qp = qn @ Wq^T + bq (fp32)
    ln_kernel<<<NQ, 256>>>(query, qn, ln_q_w, ln_q_b);
    gemm_tn_g<<<dim3(EDIM / 128, 1), 256>>>(qn, EDIM, in_proj_w, EDIM,
                                            qp, EDIM, NQ, EDIM, EDIM, in_proj_b);

    // 5) qk[h*64+q][e] = sum_d qp[q][h*128+d] * Wk[h*128+d][e]  (fp32 NN, z=h)
    gemm_nn_b<<<dim3(EDIM / 128, 1, NH), 256>>>(
        qp, EDIM, (size_t)HD,
        in_proj_w + EE, EDIM, (size_t)HD * EDIM,
        qk, EDIM, (size_t)NQ * EDIM,
        NQ, EDIM, HD);

    // 6) scores = (qk @ kv_rot_b^T) / sqrt(HD)   (tf32, z=b)
    gemm_tf32_v2<<<dim3(Lseq / 128, 2048 / 256, Bb), 256>>>(
        qk, EDIM, 0,
        kvrot, EDIM, (size_t)Lseq * EDIM,
        scores, Lseq, (size_t)2048 * Lseq,
        EDIM, isq);

    // 7) softmax
    softmax_kernel<<<Bb * NH * NQ, 256>>>(scores);

    // 8) U = attn_b @ kv_b  (tf32 TN with kvT, z=b)
    gemm_tf32_v2<<<dim3(EDIM / 128, 2048 / 256, Bb), 256>>>(
        scores, Lseq, (size_t)2048 * Lseq,
        kvT, Lseq, (size_t)EDIM * Lseq,
        U, EDIM, (size_t)2048 * EDIM,
        Lseq, 1.f);

    // 9) ctx = U @ Wv_h^T + bv  (fp32, z = b*32+h)
    vproj_g<<<dim3(1, 1, Bb * NH), 256>>>(U, in_proj_w + 2 * EE,
                                          in_proj_b + 2 * EDIM, ctx);

    // 10) out1 = ctx @ Wout^T + bout ; post-LN ; final @ proj
    gemm_tn_g<<<dim3(EDIM / 128, 1), 256>>>(ctx, EDIM, out_proj_w, EDIM,
                                            out1, EDIM, Bb * NQ, EDIM, EDIM, out_proj_b);
    ln_kernel<<<Bb * NQ, 256>>>(out1, ln2, ln_post_w, ln_post_b);
    gemm_nn_b<<<dim3(EDIM / 128, 1, 1), 256>>>(ln2, EDIM, 0, proj, EDIM, 0,
                                               out, EDIM, 0, Bb * NQ, EDIM, EDIM);
}

// round 6
// speedup vs baseline: 3.0326x; 2.5337x over previous
#include <cuda_runtime.h>
#include <cuda_fp16.h>
#include <math.h>
#include <stdint.h>

#define EDIM 4096
#define NH   32
#define HD   128
#define Lseq 8192
#define Bb   2
#define VD   1536
#define NQ   64
#define NROWS (Bb*Lseq)

// ---------------- scratch ----------------
__device__ float  g_kvraw[NROWS * EDIM];
__device__ __half g_hcube[NROWS * VD];
__device__ __half g_hw[EDIM * VD];
__device__ __half g_hkv[NROWS * EDIM];
__device__ __half g_hkvrot[NROWS * EDIM];
__device__ __half g_hkvT[(size_t)Bb * EDIM * Lseq];
__device__ float  g_scores[(size_t)Bb * 2048 * Lseq];
__device__ __half g_hattn[(size_t)Bb * 2048 * Lseq];
__device__ __half g_hqn[NQ * EDIM];
__device__ __half g_hqp[NQ * EDIM];
__device__ __half g_hqk[2048 * EDIM];
__device__ __half g_hU[(size_t)Bb * 2048 * EDIM];
__device__ __half g_hctx[128 * EDIM];
__device__ float  g_out1[128 * EDIM];
__device__ __half g_hln2[128 * EDIM];
__device__ __half g_hWq[EDIM * EDIM];
__device__ __half g_hWkT[EDIM * EDIM];
__device__ __half g_hWv[EDIM * EDIM];
__device__ __half g_hWout[EDIM * EDIM];
__device__ __half g_hprojT[EDIM * EDIM];
__device__ float  g_bc[EDIM];

// ---------------- helpers ----------------
__device__ __forceinline__ void mma_f16(float c[4], uint32_t a0, uint32_t a1,
                                        uint32_t a2, uint32_t a3,
                                        uint32_t b0, uint32_t b1) {
    asm("mma.sync.aligned.m16n8k16.row.col.f32.f16.f16.f32 "
        "{%0,%1,%2,%3}, {%4,%5,%6,%7}, {%8,%9}, {%0,%1,%2,%3};"
        : "+f"(c[0]), "+f"(c[1]), "+f"(c[2]), "+f"(c[3])
        : "r"(a0), "r"(a1), "r"(a2), "r"(a3), "r"(b0), "r"(b1));
}
__device__ __forceinline__ void store2(float* p, float a, float b) {
    *(float2*)p = make_float2(a, b);
}
__device__ __forceinline__ void store2(__half* p, float a, float b) {
    *(__half2*)p = __floats2half2_rn(a, b);
}

// ---------------- fp16 TN GEMM: C = alpha*(A . B^T) + bias ----------------
// A: MxK row-major halfs, B: NxK row-major halfs. K%32==0. Block 128x256, 8 warps 64x64.
// Guarded for M,N not multiples of tile.
#define GSM_U32 (2*2560 + 2*5120)   // 61440 bytes
template <typename OutT>
__device__ __forceinline__
void gemm_h_body(const __half* __restrict__ A, int lda,
                 const __half* __restrict__ B, int ldb,
                 OutT* __restrict__ C, int ldc,
                 int M, int N, int K,
                 const float* __restrict__ bias, float alpha, uint32_t* sm) {
    uint32_t* sA = sm;            // [2][128*20]
    uint32_t* sB = sm + 2 * 2560; // [2][256*20]
    int t = threadIdx.x, lane = t & 31, wid = t >> 5;
    int m0 = blockIdx.y * 128, n0 = blockIdx.x * 256;
    int ar = t >> 1, ah = t & 1;
    int arow = m0 + ar; if (arow >= M) arow = M - 1;
    int brow = n0 + t;  if (brow >= N) brow = N - 1;
    const __half* pA = A + (size_t)arow * lda + ah * 16;
    const __half* pB = B + (size_t)brow * ldb;
    int wm = (wid & 1) * 64, wn = (wid >> 1) * 64;
    int lr = lane >> 2, lc = lane & 3;

    float acc[4][8][4];
#pragma unroll
    for (int i = 0; i < 4; i++)
#pragma unroll
        for (int j = 0; j < 8; j++)
#pragma unroll
            for (int v = 0; v < 4; v++) acc[i][j][v] = 0.f;

    uint4 a0v = *(const uint4*)(pA);
    uint4 a1v = *(const uint4*)(pA + 8);
    uint4 b0v = *(const uint4*)(pB);
    uint4 b1v = *(const uint4*)(pB + 8);
    uint4 b2v = *(const uint4*)(pB + 16);
    uint4 b3v = *(const uint4*)(pB + 24);
    {
        uint32_t* d = &sA[ar * 20 + ah * 8];
        *(uint4*)d = a0v; *(uint4*)(d + 4) = a1v;
        uint32_t* e = &sB[t * 20];
        *(uint4*)e = b0v; *(uint4*)(e + 4) = b1v;
        *(uint4*)(e + 8) = b2v; *(uint4*)(e + 12) = b3v;
    }
    __syncthreads();

    int st = 0;
    for (int k0 = 0; k0 < K; k0 += 32) {
        bool more = (k0 + 32) < K;
        if (more) {
            a0v = *(const uint4*)(pA + k0 + 32);
            a1v = *(const uint4*)(pA + k0 + 40);
            b0v = *(const uint4*)(pB + k0 + 32);
            b1v = *(const uint4*)(pB + k0 + 40);
            b2v = *(const uint4*)(pB + k0 + 48);
            b3v = *(const uint4*)(pB + k0 + 56);
        }
        const uint32_t* as = sA + st * 2560;
        const uint32_t* bs = sB + st * 5120;
#pragma unroll
        for (int kk = 0; kk < 2; kk++) {
            int kb = kk * 8 + lc;
            uint32_t af[4][4], bf[8][2];
#pragma unroll
            for (int i = 0; i < 4; i++) {
                int row = wm + i * 16 + lr;
                af[i][0] = as[row * 20 + kb];
                af[i][1] = as[(row + 8) * 20 + kb];
                af[i][2] = as[row * 20 + kb + 4];
                af[i][3] = as[(row + 8) * 20 + kb + 4];
            }
#pragma unroll
            for (int j = 0; j < 8; j++) {
                int col = wn + j * 8 + lr;
                bf[j][0] = bs[col * 20 + kb];
                bf[j][1] = bs[col * 20 + kb + 4];
            }
#pragma unroll
            for (int i = 0; i < 4; i++)
#pragma unroll
                for (int j = 0; j < 8; j++)
                    mma_f16(acc[i][j], af[i][0], af[i][1], af[i][2], af[i][3],
                            bf[j][0], bf[j][1]);
        }
        if (more) {
            int ns = st ^ 1;
            uint32_t* d = &sA[ns * 2560 + ar * 20 + ah * 8];
            *(uint4*)d = a0v; *(uint4*)(d + 4) = a1v;
            uint32_t* e = &sB[ns * 5120 + t * 20];
            *(uint4*)e = b0v; *(uint4*)(e + 4) = b1v;
            *(uint4*)(e + 8) = b2v; *(uint4*)(e + 12) = b3v;
            __syncthreads();
            st = ns;
        }
    }

#pragma unroll
    for (int i = 0; i < 4; i++) {
        int row = m0 + wm + i * 16 + lr;
#pragma unroll
        for (int j = 0; j < 8; j++) {
            int col = n0 + wn + j * 8 + lc * 2;
            if (col >= N) continue;
            float bv0 = bias ? bias[col] : 0.f;
            float bv1 = bias ? bias[col + 1] : 0.f;
            if (row < M)
                store2(&C[(size_t)row * ldc + col],
                       acc[i][j][0] * alpha + bv0, acc[i][j][1] * alpha + bv1);
            if (row + 8 < M)
                store2(&C[(size_t)(row + 8) * ldc + col],
                       acc[i][j][2] * alpha + bv0, acc[i][j][3] * alpha + bv1);
        }
    }
}

template <typename OutT>
__global__ __launch_bounds__(256, 1)
void gemm_h(const __half* A, int lda, size_t sAz,
            const __half* B, int ldb, size_t sBz,
            OutT* C, int ldc, size_t sCz,
            int M, int N, int K, const float* bias, float alpha) {
    extern __shared__ uint32_t sm[];
    gemm_h_body<OutT>(A + (size_t)blockIdx.z * sAz, lda,
                      B + (size_t)blockIdx.z * sBz, ldb,
                      C + (size_t)blockIdx.z * sCz, ldc,
                      M, N, K, bias, alpha, sm);
}

__global__ __launch_bounds__(256, 1)
void vproj_h(const __half* U, const __half* Wv, __half* ctx) {
    extern __shared__ uint32_t sm[];
    int z = blockIdx.z;
    int b = z >> 5, h = z & 31;
    gemm_h_body<__half>(U + (size_t)z * 64 * EDIM, EDIM,
                        Wv + (size_t)h * 128 * EDIM, EDIM,
                        ctx + (size_t)b * 64 * EDIM + h * 128, EDIM,
                        64, 128, EDIM, nullptr, 1.f, sm);
}

// ---------------- elementwise / misc ----------------
__global__ void cvt_h(const float* __restrict__ in, __half* __restrict__ out, int n4) {
    int i = blockIdx.x * blockDim.x + threadIdx.x;
    if (i < n4) {
        float4 v = ((const float4*)in)[i];
        __half2 h0 = __floats2half2_rn(v.x, v.y);
        __half2 h1 = __floats2half2_rn(v.z, v.w);
        ((__half2*)out)[i * 2] = h0;
        ((__half2*)out)[i * 2 + 1] = h1;
    }
}

template <typename Tin>
__global__ void transpose_h(const Tin* __restrict__ in, __half* __restrict__ out,
                            int R, int Cc, size_t sIn, size_t sOut) {
    __shared__ __half tile[32][33];
    in += (size_t)blockIdx.z * sIn;
    out += (size_t)blockIdx.z * sOut;
    int r0 = blockIdx.x * 32, c0 = blockIdx.y * 32;
    int x = threadIdx.x, y = threadIdx.y;
    for (int i = y; i < 32; i += 8)
        tile[i][x] = (__half)(float)in[(size_t)(r0 + i) * Cc + c0 + x];
    __syncthreads();
    for (int i = y; i < 32; i += 8)
        out[(size_t)(c0 + i) * R + r0 + x] = tile[x][i];
}

__global__ void ln_rope_kernel(const float* __restrict__ kvr,
                               __half* __restrict__ hkv, __half* __restrict__ hrot,
                               const float* __restrict__ w, const float* __restrict__ b) {
    __shared__ __align__(16) float row[4096];
    __shared__ float red[256];
    int rix = blockIdx.x;
    int l = rix & (Lseq - 1);
    size_t base = (size_t)rix * 4096;
    int tid = threadIdx.x;
    float s = 0.f;
    for (int i = tid; i < 4096; i += 256) { float v = kvr[base + i]; row[i] = v; s += v; }
    red[tid] = s; __syncthreads();
    for (int off = 128; off > 0; off >>= 1) {
        if (tid < off) red[tid] += red[tid + off];
        __syncthreads();
    }
    float mean = red[0] * (1.f / 4096.f);
    __syncthreads();
    float vs = 0.f;
    for (int i = tid; i < 4096; i += 256) { float d = row[i] - mean; vs += d * d; }
    red[tid] = vs; __syncthreads();
    for (int off = 128; off > 0; off >>= 1) {
        if (tid < off) red[tid] += red[tid + off];
        __syncthreads();
    }
    float inv = rsqrtf(red[0] * (1.f / 4096.f) + 1e-6f);
    __syncthreads();

    int tt = l >> 10;
    int rem = l & 1023;
    float hh = (float)(rem >> 5);
    float ww = (float)(rem & 31);
    float pos = (float)tt * (10.0f / 3.0f);
    float lo = floorf(pos); if (lo > 23.f) lo = 23.f;
    float hi = ceilf(pos);  if (hi > 23.f) hi = 23.f;
    float wgt = pos - lo;
    float pt = lo * (1.f - wgt) + hi * wgt;

    for (int i = tid; i < 2048; i += 256) {
        int j = 2 * i;
        float x1 = (row[j] - mean) * inv * w[j] + b[j];
        float x2 = (row[j + 1] - mean) * inv * w[j + 1] + b[j + 1];
        float theta;
        if (j < 1024) {
            int k = j & 511;
            theta = pt * powf(10000.f, -(float)(2 * k) / 1024.f);
        } else if (j < 2560) {
            int k = (j - 1024) % 768;
            theta = hh * powf(10000.f, -(float)(2 * k) / 1536.f);
        } else {
            int k = (j - 2560) % 768;
            theta = ww * powf(10000.f, -(float)(2 * k) / 1536.f);
        }
        float cc = cosf(theta), ss = sinf(theta);
        *(__half2*)&hkv[base + j]  = __floats2half2_rn(x1, x2);
        *(__half2*)&hrot[base + j] = __floats2half2_rn(x1 * cc - x2 * ss,
                                                       x1 * ss + x2 * cc);
    }
}

__global__ void ln_kernel_h(const float* __restrict__ in, __half* __restrict__ out,
                            const float* __restrict__ w, const float* __restrict__ b) {
    __shared__ __align__(16) float row[4096];
    __shared__ float red[256];
    size_t base = (size_t)blockIdx.x * 4096;
    int tid = threadIdx.x;
    float s = 0.f;
    for (int i = tid; i < 4096; i += 256) { float v = in[base + i]; row[i] = v; s += v; }
    red[tid] = s; __syncthreads();
    for (int off = 128; off > 0; off >>= 1) {
        if (tid < off) red[tid] += red[tid + off];
        __syncthreads();
    }
    float mean = red[0] * (1.f / 4096.f);
    __syncthreads();
    float vs = 0.f;
    for (int i = tid; i < 4096; i += 256) { float d = row[i] - mean; vs += d * d; }
    red[tid] = vs; __syncthreads();
    for (int off = 128; off > 0; off >>= 1) {
        if (tid < off) red[tid] += red[tid + off];
        __syncthreads();
    }
    float inv = rsqrtf(red[0] * (1.f / 4096.f) + 1e-6f);
    for (int i = tid; i < 4096; i += 256)
        out[base + i] = (__half)((row[i] - mean) * inv * w[i] + b[i]);
}

__global__ void softmax_h(const float* __restrict__ s, __half* __restrict__ o) {
    __shared__ __align__(16) float rowc[Lseq];
    __shared__ float red[256];
    const float* p = s + (size_t)blockIdx.x * Lseq;
    __half* q = o + (size_t)blockIdx.x * Lseq;
    int tid = threadIdx.x;
    float mx = -1e30f;
    for (int i = tid; i < Lseq; i += 256) { float v = p[i]; rowc[i] = v; mx = fmaxf(mx, v); }
    red[tid] = mx; __syncthreads();
    for (int off = 128; off > 0; off >>= 1) {
        if (tid < off) red[tid] = fmaxf(red[tid], red[tid + off]);
        __syncthreads();
    }
    mx = red[0];
    __syncthreads();
    float sum = 0.f;
    for (int i = tid; i < Lseq; i += 256) {
        float e = expf(rowc[i] - mx);
        rowc[i] = e;
        sum += e;
    }
    red[tid] = sum; __syncthreads();
    for (int off = 128; off > 0; off >>= 1) {
        if (tid < off) red[tid] += red[tid + off];
        __syncthreads();
    }
    float inv = 1.f / red[0];
    __syncthreads();
    for (int i = tid; i < Lseq; i += 256) q[i] = (__half)(rowc[i] * inv);
}

// bc[f] = sum_e Wout[f][e]*bv[e] + bout[f]
__global__ void bias_combine(const float* __restrict__ Wout, const float* __restrict__ bv,
                             const float* __restrict__ bout, float* __restrict__ bc) {
    __shared__ float red[128];
    int f = blockIdx.x;
    int tid = threadIdx.x;
    float s = 0.f;
    for (int e = tid; e < EDIM; e += 128) s += Wout[(size_t)f * EDIM + e] * bv[e];
    red[tid] = s; __syncthreads();
    for (int off = 64; off > 0; off >>= 1) {
        if (tid < off) red[tid] += red[tid + off];
        __syncthreads();
    }
    if (tid == 0) bc[f] = red[0] + bout[f];
}

// ---------------- launch ----------------
extern "C" void kernel_launch(void* const* d_in, const int* in_sizes, int n_in,
                              void* d_out, int out_size) {
    const float* cube      = (const float*)d_in[0];
    const float* query     = (const float*)d_in[1];
    const float* kv_proj_w = (const float*)d_in[2];
    const float* ln_q_w    = (const float*)d_in[3];
    const float* ln_q_b    = (const float*)d_in[4];
    const float* ln_kv_w   = (const float*)d_in[5];
    const float* ln_kv_b   = (const float*)d_in[6];
    const float* ln_post_w = (const float*)d_in[7];
    const float* ln_post_b = (const float*)d_in[8];
    const float* in_proj_w = (const float*)d_in[9];
    const float* in_proj_b = (const float*)d_in[10];
    const float* out_proj_w= (const float*)d_in[11];
    const float* out_proj_b= (const float*)d_in[12];
    const float* proj      = (const float*)d_in[13];
    float* out = (float*)d_out;

    float *kvraw, *scores, *out1, *bc;
    __half *hcube, *hw, *hkv, *hrot, *hkvT, *hattn, *hqn, *hqp, *hqk, *hU, *hctx, *hln2;
    __half *hWq, *hWkT, *hWv, *hWout, *hprojT;
    cudaGetSymbolAddress((void**)&kvraw, g_kvraw);
    cudaGetSymbolAddress((void**)&hcube, g_hcube);
    cudaGetSymbolAddress((void**)&hw,    g_hw);
    cudaGetSymbolAddress((void**)&hkv,   g_hkv);
    cudaGetSymbolAddress((void**)&hrot,  g_hkvrot);
    cudaGetSymbolAddress((void**)&hkvT,  g_hkvT);
    cudaGetSymbolAddress((void**)&scores,g_scores);
    cudaGetSymbolAddress((void**)&hattn, g_hattn);
    cudaGetSymbolAddress((void**)&hqn,   g_hqn);
    cudaGetSymbolAddress((void**)&hqp,   g_hqp);
    cudaGetSymbolAddress((void**)&hqk,   g_hqk);
    cudaGetSymbolAddress((void**)&hU,    g_hU);
    cudaGetSymbolAddress((void**)&hctx,  g_hctx);
    cudaGetSymbolAddress((void**)&out1,  g_out1);
    cudaGetSymbolAddress((void**)&hln2,  g_hln2);
    cudaGetSymbolAddress((void**)&hWq,   g_hWq);
    cudaGetSymbolAddress((void**)&hWkT,  g_hWkT);
    cudaGetSymbolAddress((void**)&hWv,   g_hWv);
    cudaGetSymbolAddress((void**)&hWout, g_hWout);
    cudaGetSymbolAddress((void**)&hprojT,g_hprojT);
    cudaGetSymbolAddress((void**)&bc,    g_bc);

    const int SMB = GSM_U32 * 4;
    cudaFuncSetAttribute(gemm_h<float>,  cudaFuncAttributeMaxDynamicSharedMemorySize, SMB);
    cudaFuncSetAttribute(gemm_h<__half>, cudaFuncAttributeMaxDynamicSharedMemorySize, SMB);
    cudaFuncSetAttribute(vproj_h,        cudaFuncAttributeMaxDynamicSharedMemorySize, SMB);

    const size_t EE = (size_t)EDIM * EDIM;
    const float isq = 0.08838834764831845f;

    // conversions
    cvt_h<<<(NROWS * VD / 4 + 255) / 256, 256>>>(cube, hcube, NROWS * VD / 4);
    cvt_h<<<(EDIM * VD / 4 + 255) / 256, 256>>>(kv_proj_w, hw, EDIM * VD / 4);
    cvt_h<<<(int)(EE / 4 + 255) / 256, 256>>>(in_proj_w, hWq, EE / 4);
    cvt_h<<<(int)(EE / 4 + 255) / 256, 256>>>(in_proj_w + 2 * EE, hWv, EE / 4);
    cvt_h<<<(int)(EE / 4 + 255) / 256, 256>>>(out_proj_w, hWout, EE / 4);
    transpose_h<float><<<dim3(EDIM / 32, EDIM / 32, 1), dim3(32, 8)>>>(
        in_proj_w + EE, hWkT, EDIM, EDIM, 0, 0);
    transpose_h<float><<<dim3(EDIM / 32, EDIM / 32, 1), dim3(32, 8)>>>(
        proj, hprojT, EDIM, EDIM, 0, 0);
    bias_combine<<<EDIM, 128>>>(out_proj_w, in_proj_b + 2 * EDIM, out_proj_b, bc);

    // 1) kv_raw = cube @ kv_proj_w^T
    gemm_h<float><<<dim3(EDIM / 256, NROWS / 128, 1), 256, SMB>>>(
        hcube, VD, 0, hw, VD, 0, kvraw, EDIM, 0, NROWS, EDIM, VD, nullptr, 1.f);
    // 2) LN + RoPE -> hkv, hrot (fp16)
    ln_rope_kernel<<<NROWS, 256>>>(kvraw, hkv, hrot, ln_kv_w, ln_kv_b);
    // 3) kvT
    transpose_h<__half><<<dim3(Lseq / 32, EDIM / 32, Bb), dim3(32, 8)>>>(
        hkv, hkvT, Lseq, EDIM, (size_t)Lseq * EDIM, (size_t)EDIM * Lseq);

    // 4) q path
    ln_kernel_h<<<NQ, 256>>>(query, hqn, ln_q_w, ln_q_b);
    gemm_h<__half><<<dim3(EDIM / 256, 1, 1), 256, SMB>>>(
        hqn, EDIM, 0, hWq, EDIM, 0, hqp, EDIM, 0, NQ, EDIM, EDIM, in_proj_b, 1.f);
    // 5) qk[h] = qp_h @ WkT_h^T   (z = h)
    gemm_h<__half><<<dim3(EDIM / 256, 1, NH), 256, SMB>>>(
        hqp, EDIM, (size_t)HD, hWkT, EDIM, (size_t)HD,
        hqk, EDIM, (size_t)NQ * EDIM, NQ, EDIM, HD, nullptr, 1.f);
    // 6) scores = qk @ kvrot_b^T * isq   (z = b)
    gemm_h<float><<<dim3(Lseq / 256, 2048 / 128, Bb), 256, SMB>>>(
        hqk, EDIM, 0, hrot, EDIM, (size_t)Lseq * EDIM,
        scores, Lseq, (size_t)2048 * Lseq, 2048, Lseq, EDIM, nullptr, isq);
    // 7) softmax -> fp16 attn
    softmax_h<<<Bb * 2048, 256>>>(scores, hattn);
    // 8) U = attn @ kvT^T   (z = b)
    gemm_h<__half><<<dim3(EDIM / 256, 2048 / 128, Bb), 256, SMB>>>(
        hattn, Lseq, (size_t)2048 * Lseq, hkvT, Lseq, (size_t)EDIM * Lseq,
        hU, EDIM, (size_t)2048 * EDIM, 2048, EDIM, Lseq, nullptr, 1.f);
    // 9) ctx = U @ Wv_h^T   (z = b*32+h; bias folded into bc)
    vproj_h<<<dim3(1, 1, Bb * NH), 256, SMB>>>(hU, hWv, hctx);
    // 10) out1 = ctx @ Wout^T + bc
    gemm_h<float><<<dim3(EDIM / 256, 1, 1), 256, SMB>>>(
        hctx, EDIM, 0, hWout, EDIM, 0, out1, EDIM, 0, 128, EDIM, EDIM, bc, 1.f);
    // 11) post-LN -> fp16
    ln_kernel_h<<<128, 256>>>(out1, hln2, ln_post_w, ln_post_b);
    // 12) out = ln2 @ projT^T
    gemm_h<float><<<dim3(EDIM / 256, 1, 1), 256, SMB>>>(
        hln2, EDIM, 0, hprojT, EDIM, 0, out, EDIM, 0, 128, EDIM, EDIM, nullptr, 1.f);
}

// round 7
// speedup vs baseline: 3.1854x; 1.0504x over previous
#include <cuda_runtime.h>
#include <cuda_fp16.h>
#include <math.h>
#include <stdint.h>

#define EDIM 4096
#define NH   32
#define HD   128
#define Lseq 8192
#define Bb   2
#define VD   1536
#define NQ   64
#define NROWS (Bb*Lseq)

// ---------------- scratch ----------------
__device__ float  g_kvraw[NROWS * EDIM];
__device__ __half g_hcube[NROWS * VD];
__device__ __half g_hw[EDIM * VD];
__device__ __half g_hkv[NROWS * EDIM];
__device__ __half g_hrot[NROWS * EDIM];
__device__ __half g_hkvT[(size_t)Bb * EDIM * Lseq];
__device__ float  g_scores[(size_t)Bb * 2048 * Lseq];
__device__ __half g_hattn[(size_t)Bb * 2048 * Lseq];
__device__ float  g_qn[NQ * EDIM];
__device__ float  g_qp[NQ * EDIM];
__device__ float  g_qk[2048 * EDIM];
__device__ __half g_hqk[2048 * EDIM];
__device__ float  g_U[(size_t)Bb * 2048 * EDIM];
__device__ float  g_ctx[128 * EDIM];
__device__ float  g_out1[128 * EDIM];
__device__ float  g_ln2[128 * EDIM];
__device__ float  g_WkT[(size_t)EDIM * EDIM];
__device__ float  g_projT[(size_t)EDIM * EDIM];
__device__ float  g_bc[EDIM];

// ---------------- asm helpers ----------------
__device__ __forceinline__ void mma_f16(float c[4], uint32_t a0, uint32_t a1,
                                        uint32_t a2, uint32_t a3,
                                        uint32_t b0, uint32_t b1) {
    asm("mma.sync.aligned.m16n8k16.row.col.f32.f16.f16.f32 "
        "{%0,%1,%2,%3}, {%4,%5,%6,%7}, {%8,%9}, {%0,%1,%2,%3};"
        : "+f"(c[0]), "+f"(c[1]), "+f"(c[2]), "+f"(c[3])
        : "r"(a0), "r"(a1), "r"(a2), "r"(a3), "r"(b0), "r"(b1));
}
__device__ __forceinline__ void ldsm4(uint32_t& r0, uint32_t& r1, uint32_t& r2,
                                      uint32_t& r3, uint32_t a) {
    asm volatile("ldmatrix.sync.aligned.m8n8.x4.shared.b16 {%0,%1,%2,%3}, [%4];"
                 : "=r"(r0), "=r"(r1), "=r"(r2), "=r"(r3) : "r"(a));
}
__device__ __forceinline__ void cp16(uint32_t s, const void* g) {
    asm volatile("cp.async.cg.shared.global [%0], [%1], 16;" :: "r"(s), "l"(g));
}
#define CP_COMMIT() asm volatile("cp.async.commit_group;")
#define CP_WAIT0()  asm volatile("cp.async.wait_group 0;" ::: "memory")

// ---------------- fp16 TN GEMM: C(fp32) = alpha*(A . B^T) ----------------
// Block 128x256, 8 warps 64x64. M%128==0, N%256==0, K%32==0. ldmatrix + cp.async.
#define GSMB 61440
__global__ __launch_bounds__(256, 1)
void gemm_h(const __half* __restrict__ A, int lda, size_t sAz,
            const __half* __restrict__ B, int ldb, size_t sBz,
            float* __restrict__ C, int ldc, size_t sCz,
            int K, float alpha) {
    extern __shared__ __align__(16) uint32_t sm[];
    uint32_t smB = (uint32_t)__cvta_generic_to_shared(sm);
    int t = threadIdx.x, lane = t & 31, wid = t >> 5;
    A += (size_t)blockIdx.z * sAz;
    B += (size_t)blockIdx.z * sBz;
    C += (size_t)blockIdx.z * sCz;
    int m0 = blockIdx.y * 128, n0 = blockIdx.x * 256;
    int wm = (wid & 1) * 64, wn = (wid >> 1) * 64;
    int lr = lane >> 2, lc = lane & 3;

    // staging: A row ar (2 x 16B), B row t (4 x 16B); row stride 80B (20 u32)
    int ar = t >> 1, ac = (t & 1) * 2;
    const __half* gA = A + (size_t)(m0 + ar) * lda + ac * 8;
    const __half* gB = B + (size_t)(n0 + t) * ldb;
    uint32_t sAaddr = smB + ar * 80 + ac * 16;
    uint32_t sBaddr = smB + 20480 + t * 80;

    // fragment base addresses (bytes)
    uint32_t aBase = smB + (wm + (lane & 15)) * 80 + ((lane >> 4) & 1) * 16;
    uint32_t bBase = smB + 20480 +
                     (wn + (lane & 7) + ((lane >> 4) & 1) * 8) * 80 +
                     ((lane >> 3) & 1) * 16;

    float acc[4][8][4];
#pragma unroll
    for (int i = 0; i < 4; i++)
#pragma unroll
        for (int j = 0; j < 8; j++)
#pragma unroll
            for (int v = 0; v < 4; v++) acc[i][j][v] = 0.f;

    // prologue: stage 0
    cp16(sAaddr, gA); cp16(sAaddr + 16, gA + 8);
#pragma unroll
    for (int c = 0; c < 4; c++) cp16(sBaddr + c * 16, gB + c * 8);
    CP_COMMIT(); CP_WAIT0(); __syncthreads();

    int st = 0;
    for (int k0 = 0; k0 < K; k0 += 32) {
        bool more = (k0 + 32) < K;
        if (more) {
            int ns = st ^ 1;
            uint32_t d = sAaddr + ns * 10240;
            cp16(d, gA + k0 + 32); cp16(d + 16, gA + k0 + 40);
            uint32_t e = sBaddr + ns * 20480;
#pragma unroll
            for (int c = 0; c < 4; c++) cp16(e + c * 16, gB + k0 + 32 + c * 8);
            CP_COMMIT();
        }
        uint32_t sa = aBase + st * 10240;
        uint32_t sb = bBase + st * 20480;
#pragma unroll
        for (int kk = 0; kk < 2; kk++) {
            uint32_t af[4][4], bf[8][2];
#pragma unroll
            for (int i = 0; i < 4; i++)
                ldsm4(af[i][0], af[i][1], af[i][2], af[i][3],
                      sa + i * 1280 + kk * 32);
#pragma unroll
            for (int jp = 0; jp < 4; jp++)
                ldsm4(bf[2 * jp][0], bf[2 * jp][1], bf[2 * jp + 1][0],
                      bf[2 * jp + 1][1], sb + jp * 1280 + kk * 32);
#pragma unroll
            for (int i = 0; i < 4; i++)
#pragma unroll
                for (int j = 0; j < 8; j++)
                    mma_f16(acc[i][j], af[i][0], af[i][1], af[i][2], af[i][3],
                            bf[j][0], bf[j][1]);
        }
        if (more) { CP_WAIT0(); __syncthreads(); st ^= 1; }
    }

#pragma unroll
    for (int i = 0; i < 4; i++) {
        int row = m0 + wm + i * 16 + lr;
#pragma unroll
        for (int j = 0; j < 8; j++) {
            int col = n0 + wn + j * 8 + lc * 2;
            *(float2*)&C[(size_t)row * ldc + col] =
                make_float2(acc[i][j][0] * alpha, acc[i][j][1] * alpha);
            *(float2*)&C[(size_t)(row + 8) * ldc + col] =
                make_float2(acc[i][j][2] * alpha, acc[i][j][3] * alpha);
        }
    }
}

// ---------------- fp32 split-K GEMM (small), atomic accumulate ----------------
// tile 64x64, 256 threads, A: rows m, K-major; B: rows n, K-major.
__device__ __forceinline__
void sg_body(const float* __restrict__ A, int lda,
             const float* __restrict__ B, int ldb,
             float* __restrict__ C, int ldc, int n0, int Ks) {
    __shared__ float As[8][64], Bs[8][64];
    int t = threadIdx.x;
    int row = t & 63, kc = t >> 6;
    int ty = t >> 4, tx = t & 15;
    float acc[4][4];
#pragma unroll
    for (int i = 0; i < 4; i++)
#pragma unroll
        for (int j = 0; j < 4; j++) acc[i][j] = 0.f;

    for (int k0 = 0; k0 < Ks; k0 += 8) {
        float2 a = *(const float2*)&A[(size_t)row * lda + k0 + kc * 2];
        float2 b = *(const float2*)&B[(size_t)(n0 + row) * ldb + k0 + kc * 2];
        As[kc * 2][row] = a.x; As[kc * 2 + 1][row] = a.y;
        Bs[kc * 2][row] = b.x; Bs[kc * 2 + 1][row] = b.y;
        __syncthreads();
#pragma unroll
        for (int k = 0; k < 8; k++) {
            float av[4] = {As[k][ty * 4], As[k][ty * 4 + 1],
                           As[k][ty * 4 + 2], As[k][ty * 4 + 3]};
            float bv[4] = {Bs[k][tx * 4], Bs[k][tx * 4 + 1],
                           Bs[k][tx * 4 + 2], Bs[k][tx * 4 + 3]};
#pragma unroll
            for (int i = 0; i < 4; i++)
#pragma unroll
                for (int j = 0; j < 4; j++)
                    acc[i][j] = fmaf(av[i], bv[j], acc[i][j]);
        }
        __syncthreads();
    }
#pragma unroll
    for (int i = 0; i < 4; i++)
#pragma unroll
        for (int j = 0; j < 4; j++)
            atomicAdd(&C[(size_t)(ty * 4 + i) * ldc + n0 + tx * 4 + j], acc[i][j]);
}

// generic: z = K-split index, single batch. grid(N/64, M/64, nsplit)
__global__ __launch_bounds__(256)
void sg_lin(const float* A, int lda, const float* B, int ldb,
            float* C, int ldc, int Ks) {
    sg_body(A + (size_t)blockIdx.y * 64 * lda + (size_t)blockIdx.z * Ks, lda,
            B + (size_t)blockIdx.z * Ks, ldb,
            C + (size_t)blockIdx.y * 64 * ldc, ldc,
            blockIdx.x * 64, Ks);
}
// qk: z = head. qk[h*64+q][e] = sum_d qp[q][h*128+d] * WkT[e][h*128+d]
__global__ __launch_bounds__(256)
void sg_qk(const float* qp, const float* WkT, float* qk) {
    int h = blockIdx.z;
    sg_body(qp + h * 128, EDIM, WkT + h * 128, EDIM,
            qk + (size_t)h * 64 * EDIM, EDIM, blockIdx.x * 64, 128);
}
// vproj: z = (b*32+h)*4 + s. ctx[b*64+q][h*128+d] += U_bh[q][:].Wv_h[d][:]
__global__ __launch_bounds__(256)
void sg_vproj(const float* U, const float* Wv, float* ctx) {
    int z = blockIdx.z;
    int bh = z >> 2, s = z & 3;
    int b = bh >> 5, h = bh & 31;
    sg_body(U + (size_t)bh * 64 * EDIM + s * 1024, EDIM,
            Wv + (size_t)h * 128 * EDIM + s * 1024, EDIM,
            ctx + (size_t)b * 64 * EDIM + h * 128, EDIM,
            blockIdx.x * 64, 1024);
}

__global__ void init_rows(float* C, const float* bias, int ld) {
    int f = blockIdx.x * 256 + threadIdx.x;
    C[(size_t)blockIdx.y * ld + f] = bias ? bias[f] : 0.f;
}

// ---------------- elementwise / misc ----------------
__global__ void cvt_h(const float* __restrict__ in, __half* __restrict__ out, int n4) {
    int i = blockIdx.x * blockDim.x + threadIdx.x;
    if (i < n4) {
        float4 v = ((const float4*)in)[i];
        ((__half2*)out)[i * 2]     = __floats2half2_rn(v.x, v.y);
        ((__half2*)out)[i * 2 + 1] = __floats2half2_rn(v.z, v.w);
    }
}

__global__ void transpose_hh(const __half* __restrict__ in, __half* __restrict__ out,
                             int R, int Cc, size_t sIn, size_t sOut) {
    __shared__ __half tile[32][33];
    in += (size_t)blockIdx.z * sIn;
    out += (size_t)blockIdx.z * sOut;
    int r0 = blockIdx.x * 32, c0 = blockIdx.y * 32;
    int x = threadIdx.x, y = threadIdx.y;
    for (int i = y; i < 32; i += 8)
        tile[i][x] = in[(size_t)(r0 + i) * Cc + c0 + x];
    __syncthreads();
    for (int i = y; i < 32; i += 8)
        out[(size_t)(c0 + i) * R + r0 + x] = tile[x][i];
}

__global__ void transpose_ff(const float* __restrict__ in, float* __restrict__ out, int N) {
    __shared__ float tile[32][33];
    int r0 = blockIdx.x * 32, c0 = blockIdx.y * 32;
    int x = threadIdx.x, y = threadIdx.y;
    for (int i = y; i < 32; i += 8)
        tile[i][x] = in[(size_t)(r0 + i) * N + c0 + x];
    __syncthreads();
    for (int i = y; i < 32; i += 8)
        out[(size_t)(c0 + i) * N + r0 + x] = tile[x][i];
}

__global__ void ln_rope_kernel(const float* __restrict__ kvr,
                               __half* __restrict__ hkv, __half* __restrict__ hrot,
                               const float* __restrict__ w, const float* __restrict__ b) {
    __shared__ __align__(16) float row[4096];
    __shared__ float red[256];
    int rix = blockIdx.x;
    int l = rix & (Lseq - 1);
    size_t base = (size_t)rix * 4096;
    int tid = threadIdx.x;
    float s = 0.f;
    for (int i = tid; i < 4096; i += 256) { float v = kvr[base + i]; row[i] = v; s += v; }
    red[tid] = s; __syncthreads();
    for (int off = 128; off > 0; off >>= 1) {
        if (tid < off) red[tid] += red[tid + off];
        __syncthreads();
    }
    float mean = red[0] * (1.f / 4096.f);
    __syncthreads();
    float vs = 0.f;
    for (int i = tid; i < 4096; i += 256) { float d = row[i] - mean; vs += d * d; }
    red[tid] = vs; __syncthreads();
    for (int off = 128; off > 0; off >>= 1) {
        if (tid < off) red[tid] += red[tid + off];
        __syncthreads();
    }
    float inv = rsqrtf(red[0] * (1.f / 4096.f) + 1e-6f);
    __syncthreads();

    int tt = l >> 10;
    int rem = l & 1023;
    float hh = (float)(rem >> 5);
    float ww = (float)(rem & 31);
    float pos = (float)tt * (10.0f / 3.0f);
    float lo = floorf(pos); if (lo > 23.f) lo = 23.f;
    float hi = ceilf(pos);  if (hi > 23.f) hi = 23.f;
    float wgt = pos - lo;
    float pt = lo * (1.f - wgt) + hi * wgt;

    for (int i = tid; i < 2048; i += 256) {
        int j = 2 * i;
        float x1 = (row[j] - mean) * inv * w[j] + b[j];
        float x2 = (row[j + 1] - mean) * inv * w[j + 1] + b[j + 1];
        float theta;
        if (j < 1024) {
            int k = j & 511;
            theta = pt * powf(10000.f, -(float)(2 * k) / 1024.f);
        } else if (j < 2560) {
            int k = (j - 1024) % 768;
            theta = hh * powf(10000.f, -(float)(2 * k) / 1536.f);
        } else {
            int k = (j - 2560) % 768;
            theta = ww * powf(10000.f, -(float)(2 * k) / 1536.f);
        }
        float cc = cosf(theta), ss = sinf(theta);
        *(__half2*)&hkv[base + j]  = __floats2half2_rn(x1, x2);
        *(__half2*)&hrot[base + j] = __floats2half2_rn(x1 * cc - x2 * ss,
                                                       x1 * ss + x2 * cc);
    }
}

__global__ void ln_kernel(const float* __restrict__ in, float* __restrict__ out,
                          const float* __restrict__ w, const float* __restrict__ b) {
    __shared__ __align__(16) float row[4096];
    __shared__ float red[256];
    size_t base = (size_t)blockIdx.x * 4096;
    int tid = threadIdx.x;
    float s = 0.f;
    for (int i = tid; i < 4096; i += 256) { float v = in[base + i]; row[i] = v; s += v; }
    red[tid] = s; __syncthreads();
    for (int off = 128; off > 0; off >>= 1) {
        if (tid < off) red[tid] += red[tid + off];
        __syncthreads();
    }
    float mean = red[0] * (1.f / 4096.f);
    __syncthreads();
    float vs = 0.f;
    for (int i = tid; i < 4096; i += 256) { float d = row[i] - mean; vs += d * d; }
    red[tid] = vs; __syncthreads();
    for (int off = 128; off > 0; off >>= 1) {
        if (tid < off) red[tid] += red[tid + off];
        __syncthreads();
    }
    float inv = rsqrtf(red[0] * (1.f / 4096.f) + 1e-6f);
    for (int i = tid; i < 4096; i += 256)
        out[base + i] = (row[i] - mean) * inv * w[i] + b[i];
}

__global__ void softmax_h(const float* __restrict__ s, __half* __restrict__ o) {
    __shared__ __align__(16) float rowc[Lseq];
    __shared__ float red[256];
    const float* p = s + (size_t)blockIdx.x * Lseq;
    __half* q = o + (size_t)blockIdx.x * Lseq;
    int tid = threadIdx.x;
    float mx = -1e30f;
    for (int i = tid; i < Lseq; i += 256) { float v = p[i]; rowc[i] = v; mx = fmaxf(mx, v); }
    red[tid] = mx; __syncthreads();
    for (int off = 128; off > 0; off >>= 1) {
        if (tid < off) red[tid] = fmaxf(red[tid], red[tid + off]);
        __syncthreads();
    }
    mx = red[0];
    __syncthreads();
    float sum = 0.f;
    for (int i = tid; i < Lseq; i += 256) {
        float e = expf(rowc[i] - mx);
        rowc[i] = e;
        sum += e;
    }
    red[tid] = sum; __syncthreads();
    for (int off = 128; off > 0; off >>= 1) {
        if (tid < off) red[tid] += red[tid + off];
        __syncthreads();
    }
    float inv = 1.f / red[0];
    __syncthreads();
    for (int i = tid; i < Lseq; i += 256) q[i] = (__half)(rowc[i] * inv);
}

__global__ void bias_combine(const float* __restrict__ Wout, const float* __restrict__ bv,
                             const float* __restrict__ bout, float* __restrict__ bc) {
    __shared__ float red[128];
    int f = blockIdx.x;
    int tid = threadIdx.x;
    float s = 0.f;
    for (int e = tid; e < EDIM; e += 128) s += Wout[(size_t)f * EDIM + e] * bv[e];
    red[tid] = s; __syncthreads();
    for (int off = 64; off > 0; off >>= 1) {
        if (tid < off) red[tid] += red[tid + off];
        __syncthreads();
    }
    if (tid == 0) bc[f] = red[0] + bout[f];
}

// ---------------- launch ----------------
extern "C" void kernel_launch(void* const* d_in, const int* in_sizes, int n_in,
                              void* d_out, int out_size) {
    const float* cube      = (const float*)d_in[0];
    const float* query     = (const float*)d_in[1];
    const float* kv_proj_w = (const float*)d_in[2];
    const float* ln_q_w    = (const float*)d_in[3];
    const float* ln_q_b    = (const float*)d_in[4];
    const float* ln_kv_w   = (const float*)d_in[5];
    const float* ln_kv_b   = (const float*)d_in[6];
    const float* ln_post_w = (const float*)d_in[7];
    const float* ln_post_b = (const float*)d_in[8];
    const float* in_proj_w = (const float*)d_in[9];
    const float* in_proj_b = (const float*)d_in[10];
    const float* out_proj_w= (const float*)d_in[11];
    const float* out_proj_b= (const float*)d_in[12];
    const float* proj      = (const float*)d_in[13];
    float* out = (float*)d_out;

    float *kvraw, *scores, *qn, *qp, *qk, *U, *ctx, *out1, *ln2, *WkT, *projT, *bc;
    __half *hcube, *hw, *hkv, *hrot, *hkvT, *hattn, *hqk;
    cudaGetSymbolAddress((void**)&kvraw, g_kvraw);
    cudaGetSymbolAddress((void**)&hcube, g_hcube);
    cudaGetSymbolAddress((void**)&hw,    g_hw);
    cudaGetSymbolAddress((void**)&hkv,   g_hkv);
    cudaGetSymbolAddress((void**)&hrot,  g_hrot);
    cudaGetSymbolAddress((void**)&hkvT,  g_hkvT);
    cudaGetSymbolAddress((void**)&scores,g_scores);
    cudaGetSymbolAddress((void**)&hattn, g_hattn);
    cudaGetSymbolAddress((void**)&qn,    g_qn);
    cudaGetSymbolAddress((void**)&qp,    g_qp);
    cudaGetSymbolAddress((void**)&qk,    g_qk);
    cudaGetSymbolAddress((void**)&hqk,   g_hqk);
    cudaGetSymbolAddress((void**)&U,     g_U);
    cudaGetSymbolAddress((void**)&ctx,   g_ctx);
    cudaGetSymbolAddress((void**)&out1,  g_out1);
    cudaGetSymbolAddress((void**)&ln2,   g_ln2);
    cudaGetSymbolAddress((void**)&WkT,   g_WkT);
    cudaGetSymbolAddress((void**)&projT, g_projT);
    cudaGetSymbolAddress((void**)&bc,    g_bc);

    cudaFuncSetAttribute(gemm_h, cudaFuncAttributeMaxDynamicSharedMemorySize, GSMB);

    const size_t EE = (size_t)EDIM * EDIM;
    const float isq = 0.08838834764831845f;

    // conversions / prep
    cvt_h<<<(NROWS * VD / 4 + 255) / 256, 256>>>(cube, hcube, NROWS * VD / 4);
    cvt_h<<<(EDIM * VD / 4 + 255) / 256, 256>>>(kv_proj_w, hw, EDIM * VD / 4);
    transpose_ff<<<dim3(EDIM / 32, EDIM / 32), dim3(32, 8)>>>(in_proj_w + EE, WkT, EDIM);
    transpose_ff<<<dim3(EDIM / 32, EDIM / 32), dim3(32, 8)>>>(proj, projT, EDIM);
    bias_combine<<<EDIM, 128>>>(out_proj_w, in_proj_b + 2 * EDIM, out_proj_b, bc);

    // 1) kvraw = cube @ kv_proj_w^T (fp16 MMA, fp32 out)
    gemm_h<<<dim3(EDIM / 256, NROWS / 128, 1), 256, GSMB>>>(
        hcube, VD, 0, hw, VD, 0, kvraw, EDIM, 0, VD, 1.f);
    // 2) LN + RoPE -> hkv, hrot
    ln_rope_kernel<<<NROWS, 256>>>(kvraw, hkv, hrot, ln_kv_w, ln_kv_b);
    // 3) hkvT
    transpose_hh<<<dim3(Lseq / 32, EDIM / 32, Bb), dim3(32, 8)>>>(
        hkv, hkvT, Lseq, EDIM, (size_t)Lseq * EDIM, (size_t)EDIM * Lseq);

    // 4) q path (fp32): qn = LN(query); qp = qn@Wq^T + bq
    ln_kernel<<<NQ, 256>>>(query, qn, ln_q_w, ln_q_b);
    init_rows<<<dim3(EDIM / 256, NQ), 256>>>(qp, in_proj_b, EDIM);
    sg_lin<<<dim3(EDIM / 64, 1, 8), 256>>>(qn, EDIM, in_proj_w, EDIM, qp, EDIM, 512);
    // 5) qk (fp32, per head), then fp16 copy
    init_rows<<<dim3(EDIM / 256, 2048), 256>>>(qk, nullptr, EDIM);
    sg_qk<<<dim3(EDIM / 64, 1, NH), 256>>>(qp, WkT, qk);
    cvt_h<<<(2048 * EDIM / 4 + 255) / 256, 256>>>(qk, hqk, 2048 * EDIM / 4);

    // 6) scores = hqk @ hrot_b^T * isq
    gemm_h<<<dim3(Lseq / 256, 2048 / 128, Bb), 256, GSMB>>>(
        hqk, EDIM, 0, hrot, EDIM, (size_t)Lseq * EDIM,
        scores, Lseq, (size_t)2048 * Lseq, EDIM, isq);
    // 7) softmax -> fp16
    softmax_h<<<Bb * 2048, 256>>>(scores, hattn);
    // 8) U = attn @ kvT^T (fp32 out)
    gemm_h<<<dim3(EDIM / 256, 2048 / 128, Bb), 256, GSMB>>>(
        hattn, Lseq, (size_t)2048 * Lseq, hkvT, Lseq, (size_t)EDIM * Lseq,
        U, EDIM, (size_t)2048 * EDIM, Lseq, 1.f);

    // 9) ctx = U @ Wv_h^T (fp32)
    init_rows<<<dim3(EDIM / 256, 128), 256>>>(ctx, nullptr, EDIM);
    sg_vproj<<<dim3(2, 1, Bb * NH * 4), 256>>>(U, in_proj_w + 2 * EE, ctx);
    // 10) out1 = ctx @ Wout^T + bc (fp32)
    init_rows<<<dim3(EDIM / 256, 128), 256>>>(out1, bc, EDIM);
    sg_lin<<<dim3(EDIM / 64, 2, 8), 256>>>(ctx, EDIM, out_proj_w, EDIM, out1, EDIM, 512);
    // 11) post-LN (fp32)
    ln_kernel<<<128, 256>>>(out1, ln2, ln_post_w, ln_post_b);
    // 12) out = ln2 @ projT^T (fp32)
    init_rows<<<dim3(EDIM / 256, 128), 256>>>(out, nullptr, EDIM);
    sg_lin<<<dim3(EDIM / 64, 2, 8), 256>>>(ln2, EDIM, projT, EDIM, out, EDIM, 512);
}